// round 2
// baseline (speedup 1.0000x reference)
#include <cuda_runtime.h>
#include <cuda_bf16.h>

#define NB   8
#define SXN  8192
#define CYC  256
#define SYN  2048
#define SPAD 68

// ---------------- device scratch (no runtime allocation) -------------------
__device__ __align__(16) float g_wt [CYC * 64];              // [c][n] n<32: wq^T, n>=32: wk^T
__device__ __align__(16) float g_wvt[64 * 64];               // [c][n] = wv[n][c]
__device__ __align__(16) float g_qk [(size_t)NB * SYN * 64]; // [b][s][0:32]=q, [32:64]=k
__device__ __align__(16) float g_vp [(size_t)NB * SYN * 64]; // [b][j][c]
__device__ __align__(16) float g_o  [(size_t)NB * 64 * SYN]; // [b][c][i]
__device__ float g_scale[64];
__device__ float g_shift[64];

// ---------------- f32x2 helpers --------------------------------------------
__device__ __forceinline__ float2 ffma2(float2 a, float2 b, float2 c) {
    unsigned long long ra = *reinterpret_cast<unsigned long long*>(&a);
    unsigned long long rb = *reinterpret_cast<unsigned long long*>(&b);
    unsigned long long rc = *reinterpret_cast<unsigned long long*>(&c);
    unsigned long long rd;
    asm("fma.rn.f32x2 %0, %1, %2, %3;" : "=l"(rd) : "l"(ra), "l"(rb), "l"(rc));
    return *reinterpret_cast<float2*>(&rd);
}
__device__ __forceinline__ float2 fdup(float x) { return make_float2(x, x); }

// ---------------- K0: weight transposes ------------------------------------
__global__ void k0_transpose(const float* __restrict__ wq,
                             const float* __restrict__ wk,
                             const float* __restrict__ wv) {
    int id = blockIdx.x * 256 + threadIdx.x;
    if (id < 16384) {                       // 256 c x 64 n
        int c = id & 255, n = id >> 8;
        g_wt[c * 64 + n] = (n < 32) ? wq[n * 256 + c] : wk[(n - 32) * 256 + c];
    } else if (id < 20480) {                // 64 c x 64 n
        int i2 = id - 16384;
        int c = i2 & 63, n = i2 >> 6;
        g_wvt[c * 64 + n] = wv[n * 64 + c];
    }
}

// ---------------- K1: q/k projection GEMM ----------------------------------
// g_qk[b][s][n] = sum_c y[b][c][s] * g_wt[c][n] + bias(n)
__global__ __launch_bounds__(256) void k1_proj_qk(const float* __restrict__ y,
                                                  const float* __restrict__ bq,
                                                  const float* __restrict__ bk) {
    __shared__ __align__(16) float As[16][128];
    __shared__ __align__(16) float Bs[16][68];
    const int b  = blockIdx.y;
    const int s0 = blockIdx.x * 128;
    const int t  = threadIdx.x;
    const int tm = t & 15, tn = t >> 4;
    const int lk = t >> 4, lm = (t & 15) * 8;
    const int bn = t & 63, bk4 = t >> 6;
    float2 acc[8][2];
#pragma unroll
    for (int i = 0; i < 8; i++) { acc[i][0] = make_float2(0.f, 0.f); acc[i][1] = make_float2(0.f, 0.f); }
    const float* yb = y + (size_t)b * CYC * SYN + s0;

    for (int c0 = 0; c0 < CYC; c0 += 16) {
        float4 va = *(const float4*)(yb + (size_t)(c0 + lk) * SYN + lm);
        float4 vb = *(const float4*)(yb + (size_t)(c0 + lk) * SYN + lm + 4);
        float w4[4];
#pragma unroll
        for (int e = 0; e < 4; e++) w4[e] = g_wt[(size_t)(c0 + bk4 * 4 + e) * 64 + bn];
        __syncthreads();
        *(float4*)&As[lk][lm]     = va;
        *(float4*)&As[lk][lm + 4] = vb;
#pragma unroll
        for (int e = 0; e < 4; e++) Bs[bk4 * 4 + e][bn] = w4[e];
        __syncthreads();
#pragma unroll
        for (int k = 0; k < 16; k++) {
            float4 a0 = *(const float4*)&As[k][tm * 4];
            float4 a1 = *(const float4*)&As[k][64 + tm * 4];
            float4 bb = *(const float4*)&Bs[k][tn * 4];
            float2 b01 = make_float2(bb.x, bb.y);
            float2 b23 = make_float2(bb.z, bb.w);
            float am[8] = {a0.x, a0.y, a0.z, a0.w, a1.x, a1.y, a1.z, a1.w};
#pragma unroll
            for (int mi = 0; mi < 8; mi++) {
                float2 ad = fdup(am[mi]);
                acc[mi][0] = ffma2(ad, b01, acc[mi][0]);
                acc[mi][1] = ffma2(ad, b23, acc[mi][1]);
            }
        }
    }
    const int n0 = tn * 4;
    float bias[4];
#pragma unroll
    for (int e = 0; e < 4; e++) { int n = n0 + e; bias[e] = (n < 32) ? bq[n] : bk[n - 32]; }
#pragma unroll
    for (int mi = 0; mi < 8; mi++) {
        int m = (mi < 4) ? (tm * 4 + mi) : (64 + tm * 4 + (mi - 4));
        float4 o = make_float4(acc[mi][0].x + bias[0], acc[mi][0].y + bias[1],
                               acc[mi][1].x + bias[2], acc[mi][1].y + bias[3]);
        *(float4*)&g_qk[((size_t)b * SYN + s0 + m) * 64 + n0] = o;
    }
}

// ---------------- K2: pooled v projection GEMM ------------------------------
// g_vp[b][j][n] = sum_c (sum_{e<4} x[b][c][4j+e]) * g_wvt[c][n] + 4*bv[n]
__global__ __launch_bounds__(256) void k2_proj_v(const float* __restrict__ x,
                                                 const float* __restrict__ bv) {
    __shared__ __align__(16) float As[16][128];
    __shared__ __align__(16) float Bs[16][68];
    const int b  = blockIdx.y;
    const int j0 = blockIdx.x * 128;
    const int t  = threadIdx.x;
    const int tm = t & 15, tn = t >> 4;
    const int lr = t >> 4;   // channel row within k-chunk
    const int f4 = t & 15;   // pooled-j column group
    const int bn = t & 63, bk4 = t >> 6;
    float2 acc[8][2];
#pragma unroll
    for (int i = 0; i < 8; i++) { acc[i][0] = make_float2(0.f, 0.f); acc[i][1] = make_float2(0.f, 0.f); }

    for (int c0 = 0; c0 < 64; c0 += 16) {
        const float* xb = x + ((size_t)b * 64 + c0 + lr) * SXN + (size_t)j0 * 4;
        float av[8];
#pragma unroll
        for (int e = 0; e < 8; e++) {
            float4 v = *(const float4*)(xb + (size_t)(f4 + 16 * e) * 4);
            av[e] = (v.x + v.y) + (v.z + v.w);
        }
        float w4[4];
#pragma unroll
        for (int e = 0; e < 4; e++) w4[e] = g_wvt[(size_t)(c0 + bk4 * 4 + e) * 64 + bn];
        __syncthreads();
#pragma unroll
        for (int e = 0; e < 8; e++) As[lr][f4 + 16 * e] = av[e];
#pragma unroll
        for (int e = 0; e < 4; e++) Bs[bk4 * 4 + e][bn] = w4[e];
        __syncthreads();
#pragma unroll
        for (int k = 0; k < 16; k++) {
            float4 a0 = *(const float4*)&As[k][tm * 4];
            float4 a1 = *(const float4*)&As[k][64 + tm * 4];
            float4 bb = *(const float4*)&Bs[k][tn * 4];
            float2 b01 = make_float2(bb.x, bb.y);
            float2 b23 = make_float2(bb.z, bb.w);
            float am[8] = {a0.x, a0.y, a0.z, a0.w, a1.x, a1.y, a1.z, a1.w};
#pragma unroll
            for (int mi = 0; mi < 8; mi++) {
                float2 ad = fdup(am[mi]);
                acc[mi][0] = ffma2(ad, b01, acc[mi][0]);
                acc[mi][1] = ffma2(ad, b23, acc[mi][1]);
            }
        }
    }
    const int n0 = tn * 4;
    float bias[4];
#pragma unroll
    for (int e = 0; e < 4; e++) bias[e] = 4.0f * bv[n0 + e];
#pragma unroll
    for (int mi = 0; mi < 8; mi++) {
        int m = (mi < 4) ? (tm * 4 + mi) : (64 + tm * 4 + (mi - 4));
        float4 o = make_float4(acc[mi][0].x + bias[0], acc[mi][0].y + bias[1],
                               acc[mi][1].x + bias[2], acc[mi][1].y + bias[3]);
        *(float4*)&g_vp[((size_t)b * SYN + j0 + m) * 64 + n0] = o;
    }
}

// ---------------- K3: flash attention + PV -----------------------------------
// Per CTA: 64 query rows. Tiles of 64 keys. Online softmax. O written [b][c][i].
__global__ __launch_bounds__(256, 2) void k3_attn() {
    extern __shared__ float smbuf[];
    float (*Qs)[SPAD] = (float(*)[SPAD])smbuf;        // [32][SPAD]
    float (*Ks)[SPAD] = Qs + 32;                      // [32][SPAD]
    float (*Ss)[SPAD] = Ks + 32;                      // [64][SPAD]
    float (*Vs)[SPAD] = Ss + 64;                      // [64][SPAD]
    float* sm_f = (float*)(Vs + 64);                  // [64]
    float* sm_l = sm_f + 64;                          // [64]

    const int b  = blockIdx.y;
    const int i0 = blockIdx.x * 64;
    const int t  = threadIdx.x;
    const float* qkb = g_qk + (size_t)b * SYN * 64;

    // load Q tile transposed: Qs[d][i]
#pragma unroll
    for (int u = 0; u < 8; u++) {
        int idx = t + 256 * u;
        int i = idx >> 5, d = idx & 31;
        Qs[d][i] = qkb[(size_t)(i0 + i) * 64 + d];
    }

    // thread mappings
    const int tr = t >> 4, tc = t & 15;               // QK: rows 4tr..+3, cols 4tc..+3
    const int sr = t >> 2, sq = t & 3;                // softmax: row sr, j-quarter sq
    const int rg = (t >> 2) & 15;                     // PV rows
    const int cg = (t & 3) | ((t >> 6) << 2);         // PV channels
    const int r0 = rg * 4, c0 = cg * 4;

    float m_i = -1e30f, l_i = 0.f;
    float2 acc[4][2];
#pragma unroll
    for (int r = 0; r < 4; r++) { acc[r][0] = make_float2(0.f, 0.f); acc[r][1] = make_float2(0.f, 0.f); }

    for (int jt = 0; jt < 32; jt++) {
        const int j0 = jt * 64;
        __syncthreads();   // prev tile's PV done with Ss/Vs
        // load K tile transposed: Ks[d][j]
#pragma unroll
        for (int u = 0; u < 8; u++) {
            int idx = t + 256 * u;
            int j = idx >> 5, d = idx & 31;
            Ks[d][j] = qkb[(size_t)(j0 + j) * 64 + 32 + d];
        }
        // load V tile: Vs[j][c]
        const float* vpb = g_vp + ((size_t)b * SYN + j0) * 64;
#pragma unroll
        for (int u = 0; u < 4; u++) {
            int idx = t + 256 * u;
            int j = idx >> 4, c = (idx & 15) * 4;
            *(float4*)&Vs[j][c] = *(const float4*)(vpb + (size_t)j * 64 + c);
        }
        __syncthreads();

        // QK^T: 4x4 register tile
        float2 s2[4][2];
#pragma unroll
        for (int r = 0; r < 4; r++) { s2[r][0] = make_float2(0.f, 0.f); s2[r][1] = make_float2(0.f, 0.f); }
#pragma unroll
        for (int d = 0; d < 32; d++) {
            float4 q4 = *(const float4*)&Qs[d][tr * 4];
            float4 k4 = *(const float4*)&Ks[d][tc * 4];
            float2 k01 = make_float2(k4.x, k4.y);
            float2 k23 = make_float2(k4.z, k4.w);
            float qa[4] = {q4.x, q4.y, q4.z, q4.w};
#pragma unroll
            for (int r = 0; r < 4; r++) {
                float2 qd = fdup(qa[r]);
                s2[r][0] = ffma2(qd, k01, s2[r][0]);
                s2[r][1] = ffma2(qd, k23, s2[r][1]);
            }
        }
#pragma unroll
        for (int r = 0; r < 4; r++) {
            float4 o = make_float4(s2[r][0].x, s2[r][0].y, s2[r][1].x, s2[r][1].y);
            *(float4*)&Ss[tr * 4 + r][tc * 4] = o;
        }
        __syncthreads();

        // online softmax: 4 threads per row (same warp quad), 16 cols each
        float4 pv[4];
        float mx = -1e30f;
#pragma unroll
        for (int u = 0; u < 4; u++) {
            pv[u] = *(const float4*)&Ss[sr][sq * 16 + u * 4];
            mx = fmaxf(mx, fmaxf(fmaxf(pv[u].x, pv[u].y), fmaxf(pv[u].z, pv[u].w)));
        }
        mx = fmaxf(mx, __shfl_xor_sync(0xFFFFFFFFu, mx, 1));
        mx = fmaxf(mx, __shfl_xor_sync(0xFFFFFFFFu, mx, 2));
        const float mnew = fmaxf(m_i, mx);
        const float fac  = __expf(m_i - mnew);
        float ssum = 0.f;
#pragma unroll
        for (int u = 0; u < 4; u++) {
            pv[u].x = __expf(pv[u].x - mnew);
            pv[u].y = __expf(pv[u].y - mnew);
            pv[u].z = __expf(pv[u].z - mnew);
            pv[u].w = __expf(pv[u].w - mnew);
            ssum += (pv[u].x + pv[u].y) + (pv[u].z + pv[u].w);
            *(float4*)&Ss[sr][sq * 16 + u * 4] = pv[u];
        }
        ssum += __shfl_xor_sync(0xFFFFFFFFu, ssum, 1);
        ssum += __shfl_xor_sync(0xFFFFFFFFu, ssum, 2);
        l_i = l_i * fac + ssum;
        m_i = mnew;
        if (sq == 0) { sm_f[sr] = fac; sm_l[sr] = l_i; }
        __syncthreads();

        // PV: thread owns 4 rows x 4 channels
        float fr[4];
#pragma unroll
        for (int r = 0; r < 4; r++) fr[r] = sm_f[r0 + r];
#pragma unroll
        for (int r = 0; r < 4; r++) {
            float2 fd = fdup(fr[r]);
            acc[r][0] = make_float2(acc[r][0].x * fd.x, acc[r][0].y * fd.x);
            acc[r][1] = make_float2(acc[r][1].x * fd.x, acc[r][1].y * fd.x);
        }
#pragma unroll
        for (int jg = 0; jg < 16; jg++) {
            float4 p4[4];
#pragma unroll
            for (int r = 0; r < 4; r++) p4[r] = *(const float4*)&Ss[r0 + r][jg * 4];
#pragma unroll
            for (int jj = 0; jj < 4; jj++) {
                float4 v4 = *(const float4*)&Vs[jg * 4 + jj][c0];
                float2 vlo = make_float2(v4.x, v4.y);
                float2 vhi = make_float2(v4.z, v4.w);
#pragma unroll
                for (int r = 0; r < 4; r++) {
                    float pj = (jj == 0) ? p4[r].x : (jj == 1) ? p4[r].y : (jj == 2) ? p4[r].z : p4[r].w;
                    float2 pd = fdup(pj);
                    acc[r][0] = ffma2(pd, vlo, acc[r][0]);
                    acc[r][1] = ffma2(pd, vhi, acc[r][1]);
                }
            }
        }
    }

    // epilogue: divide by l, store g_o[b][c][i]
    float* ob = g_o + (size_t)b * 64 * SYN;
#pragma unroll
    for (int r = 0; r < 4; r++) {
        float inv = 1.0f / sm_l[r0 + r];
        int i = i0 + r0 + r;
        ob[(size_t)(c0 + 0) * SYN + i] = acc[r][0].x * inv;
        ob[(size_t)(c0 + 1) * SYN + i] = acc[r][0].y * inv;
        ob[(size_t)(c0 + 2) * SYN + i] = acc[r][1].x * inv;
        ob[(size_t)(c0 + 3) * SYN + i] = acc[r][1].y * inv;
    }
}

// ---------------- K4: BN stats -> per-channel scale/shift -------------------
__global__ void k4_stats(const float* __restrict__ gamma,
                         const float* __restrict__ bn_w,
                         const float* __restrict__ bn_b) {
    __shared__ float rs[256], rq[256];
    const int c = blockIdx.x;
    const int t = threadIdx.x;
    float s = 0.f, s2 = 0.f;
    for (int b = 0; b < NB; b++) {
        const float* p = g_o + ((size_t)b * 64 + c) * SYN + t * 8;
#pragma unroll
        for (int u = 0; u < 2; u++) {
            float4 v = *(const float4*)(p + u * 4);
            s  += (v.x + v.y) + (v.z + v.w);
            s2 += (v.x * v.x + v.y * v.y) + (v.z * v.z + v.w * v.w);
        }
    }
    rs[t] = s; rq[t] = s2;
    __syncthreads();
    for (int st = 128; st > 0; st >>= 1) {
        if (t < st) { rs[t] += rs[t + st]; rq[t] += rq[t + st]; }
        __syncthreads();
    }
    if (t == 0) {
        const float N = 16384.f;
        float mean = rs[0] / N;
        float var  = rq[0] / N - mean * mean;
        float g = gamma[0];
        float inv = rsqrtf(g * g * var + 1e-5f);
        float sc = g * inv * bn_w[c];
        g_scale[c] = sc;
        g_shift[c] = bn_b[c] - mean * sc;
    }
}

// ---------------- K5: out = x + scale[c]*O[i>>2] + shift[c] ------------------
__global__ void k5_out(const float* __restrict__ x, float* __restrict__ out) {
    int idx = blockIdx.x * 256 + threadIdx.x;     // float4 index, < 1048576
    int c = (idx >> 11) & 63;
    float o = g_o[idx];                            // exact flat mapping (see analysis)
    float sc = g_scale[c], sh = g_shift[c];
    float add = fmaf(sc, o, sh);
    float4 xv = ((const float4*)x)[idx];
    float4 r = make_float4(xv.x + add, xv.y + add, xv.z + add, xv.w + add);
    ((float4*)out)[idx] = r;
}

// ---------------- launcher ---------------------------------------------------
extern "C" void kernel_launch(void* const* d_in, const int* in_sizes, int n_in,
                              void* d_out, int out_size) {
    const float* x     = (const float*)d_in[0];
    const float* y     = (const float*)d_in[1];
    const float* wq    = (const float*)d_in[2];
    const float* bq    = (const float*)d_in[3];
    const float* wk    = (const float*)d_in[4];
    const float* bk    = (const float*)d_in[5];
    const float* wv    = (const float*)d_in[6];
    const float* bv    = (const float*)d_in[7];
    const float* gamma = (const float*)d_in[8];
    const float* bn_w  = (const float*)d_in[9];
    const float* bn_b  = (const float*)d_in[10];
    float* out = (float*)d_out;

    const int k3_smem = (32 + 32 + 64 + 64) * SPAD * 4 + 2 * 64 * 4;  // 52736 B
    cudaFuncSetAttribute(k3_attn, cudaFuncAttributeMaxDynamicSharedMemorySize, k3_smem);

    k0_transpose<<<80, 256>>>(wq, wk, wv);
    k1_proj_qk<<<dim3(16, NB), 256>>>(y, bq, bk);
    k2_proj_v<<<dim3(16, NB), 256>>>(x, bv);
    k3_attn<<<dim3(32, NB), 256, k3_smem>>>();
    k4_stats<<<64, 256>>>(gamma, bn_w, bn_b);
    k5_out<<<4096, 256>>>(x, out);
}

// round 3
// speedup vs baseline: 1.1642x; 1.1642x over previous
#include <cuda_runtime.h>
#include <cuda_bf16.h>

#define NB   8
#define SXN  8192
#define CYC  256
#define SYN  2048
#define SPAD 68

// ---------------- device scratch (no runtime allocation) -------------------
__device__ __align__(16) float g_wt [CYC * 64];              // [c][n] n<32: wq^T, n>=32: wk^T
__device__ __align__(16) float g_wvt[64 * 64];               // [c][n] = wv[n][c]
__device__ __align__(16) float g_qk [(size_t)NB * SYN * 64]; // [b][s][0:32]=q, [32:64]=k
__device__ __align__(16) float g_vp [(size_t)NB * SYN * 64]; // [b][j][c]
__device__ __align__(16) float g_o  [(size_t)NB * 64 * SYN]; // [b][c][i]
__device__ float g_scale[64];
__device__ float g_shift[64];

// ---------------- helpers ----------------------------------------------------
__device__ __forceinline__ float2 ffma2(float2 a, float2 b, float2 c) {
    unsigned long long ra = *reinterpret_cast<unsigned long long*>(&a);
    unsigned long long rb = *reinterpret_cast<unsigned long long*>(&b);
    unsigned long long rc = *reinterpret_cast<unsigned long long*>(&c);
    unsigned long long rd;
    asm("fma.rn.f32x2 %0, %1, %2, %3;" : "=l"(rd) : "l"(ra), "l"(rb), "l"(rc));
    return *reinterpret_cast<float2*>(&rd);
}
__device__ __forceinline__ float2 fdup(float x) { return make_float2(x, x); }

__device__ __forceinline__ void cp_async4(unsigned s, const float* g) {
    asm volatile("cp.async.ca.shared.global [%0], [%1], 4;" :: "r"(s), "l"(g));
}
__device__ __forceinline__ void cp_async16(unsigned s, const float* g) {
    asm volatile("cp.async.cg.shared.global [%0], [%1], 16;" :: "r"(s), "l"(g));
}
__device__ __forceinline__ void cp_commit() { asm volatile("cp.async.commit_group;"); }
__device__ __forceinline__ void cp_wait_all() { asm volatile("cp.async.wait_group 0;"); }

// ---------------- K0: weight transposes ------------------------------------
__global__ void k0_transpose(const float* __restrict__ wq,
                             const float* __restrict__ wk,
                             const float* __restrict__ wv) {
    int id = blockIdx.x * 256 + threadIdx.x;
    if (id < 16384) {
        int c = id & 255, n = id >> 8;
        g_wt[c * 64 + n] = (n < 32) ? wq[n * 256 + c] : wk[(n - 32) * 256 + c];
    } else if (id < 20480) {
        int i2 = id - 16384;
        int c = i2 & 63, n = i2 >> 6;
        g_wvt[c * 64 + n] = wv[n * 64 + c];
    }
}

// ---------------- K1: q/k projection GEMM ----------------------------------
__global__ __launch_bounds__(256) void k1_proj_qk(const float* __restrict__ y,
                                                  const float* __restrict__ bq,
                                                  const float* __restrict__ bk) {
    __shared__ __align__(16) float As[16][128];
    __shared__ __align__(16) float Bs[16][68];
    const int b  = blockIdx.y;
    const int s0 = blockIdx.x * 128;
    const int t  = threadIdx.x;
    const int tm = t & 15, tn = t >> 4;
    const int lk = t >> 4, lm = (t & 15) * 8;
    const int bn = t & 63, bk4 = t >> 6;
    float2 acc[8][2];
#pragma unroll
    for (int i = 0; i < 8; i++) { acc[i][0] = make_float2(0.f, 0.f); acc[i][1] = make_float2(0.f, 0.f); }
    const float* yb = y + (size_t)b * CYC * SYN + s0;

    for (int c0 = 0; c0 < CYC; c0 += 16) {
        float4 va = *(const float4*)(yb + (size_t)(c0 + lk) * SYN + lm);
        float4 vb = *(const float4*)(yb + (size_t)(c0 + lk) * SYN + lm + 4);
        float w4[4];
#pragma unroll
        for (int e = 0; e < 4; e++) w4[e] = g_wt[(size_t)(c0 + bk4 * 4 + e) * 64 + bn];
        __syncthreads();
        *(float4*)&As[lk][lm]     = va;
        *(float4*)&As[lk][lm + 4] = vb;
#pragma unroll
        for (int e = 0; e < 4; e++) Bs[bk4 * 4 + e][bn] = w4[e];
        __syncthreads();
#pragma unroll
        for (int k = 0; k < 16; k++) {
            float4 a0 = *(const float4*)&As[k][tm * 4];
            float4 a1 = *(const float4*)&As[k][64 + tm * 4];
            float4 bb = *(const float4*)&Bs[k][tn * 4];
            float2 b01 = make_float2(bb.x, bb.y);
            float2 b23 = make_float2(bb.z, bb.w);
            float am[8] = {a0.x, a0.y, a0.z, a0.w, a1.x, a1.y, a1.z, a1.w};
#pragma unroll
            for (int mi = 0; mi < 8; mi++) {
                float2 ad = fdup(am[mi]);
                acc[mi][0] = ffma2(ad, b01, acc[mi][0]);
                acc[mi][1] = ffma2(ad, b23, acc[mi][1]);
            }
        }
    }
    const int n0 = tn * 4;
    float bias[4];
#pragma unroll
    for (int e = 0; e < 4; e++) { int n = n0 + e; bias[e] = (n < 32) ? bq[n] : bk[n - 32]; }
#pragma unroll
    for (int mi = 0; mi < 8; mi++) {
        int m = (mi < 4) ? (tm * 4 + mi) : (64 + tm * 4 + (mi - 4));
        float4 o = make_float4(acc[mi][0].x + bias[0], acc[mi][0].y + bias[1],
                               acc[mi][1].x + bias[2], acc[mi][1].y + bias[3]);
        *(float4*)&g_qk[((size_t)b * SYN + s0 + m) * 64 + n0] = o;
    }
}

// ---------------- K2: pooled v projection GEMM ------------------------------
__global__ __launch_bounds__(256) void k2_proj_v(const float* __restrict__ x,
                                                 const float* __restrict__ bv) {
    __shared__ __align__(16) float As[16][128];
    __shared__ __align__(16) float Bs[16][68];
    const int b  = blockIdx.y;
    const int j0 = blockIdx.x * 128;
    const int t  = threadIdx.x;
    const int tm = t & 15, tn = t >> 4;
    const int lr = t >> 4;
    const int f4 = t & 15;
    const int bn = t & 63, bk4 = t >> 6;
    float2 acc[8][2];
#pragma unroll
    for (int i = 0; i < 8; i++) { acc[i][0] = make_float2(0.f, 0.f); acc[i][1] = make_float2(0.f, 0.f); }

    for (int c0 = 0; c0 < 64; c0 += 16) {
        const float* xb = x + ((size_t)b * 64 + c0 + lr) * SXN + (size_t)j0 * 4;
        float av[8];
#pragma unroll
        for (int e = 0; e < 8; e++) {
            float4 v = *(const float4*)(xb + (size_t)(f4 + 16 * e) * 4);
            av[e] = (v.x + v.y) + (v.z + v.w);
        }
        float w4[4];
#pragma unroll
        for (int e = 0; e < 4; e++) w4[e] = g_wvt[(size_t)(c0 + bk4 * 4 + e) * 64 + bn];
        __syncthreads();
#pragma unroll
        for (int e = 0; e < 8; e++) As[lr][f4 + 16 * e] = av[e];
#pragma unroll
        for (int e = 0; e < 4; e++) Bs[bk4 * 4 + e][bn] = w4[e];
        __syncthreads();
#pragma unroll
        for (int k = 0; k < 16; k++) {
            float4 a0 = *(const float4*)&As[k][tm * 4];
            float4 a1 = *(const float4*)&As[k][64 + tm * 4];
            float4 bb = *(const float4*)&Bs[k][tn * 4];
            float2 b01 = make_float2(bb.x, bb.y);
            float2 b23 = make_float2(bb.z, bb.w);
            float am[8] = {a0.x, a0.y, a0.z, a0.w, a1.x, a1.y, a1.z, a1.w};
#pragma unroll
            for (int mi = 0; mi < 8; mi++) {
                float2 ad = fdup(am[mi]);
                acc[mi][0] = ffma2(ad, b01, acc[mi][0]);
                acc[mi][1] = ffma2(ad, b23, acc[mi][1]);
            }
        }
    }
    const int n0 = tn * 4;
    float bias[4];
#pragma unroll
    for (int e = 0; e < 4; e++) bias[e] = 4.0f * bv[n0 + e];
#pragma unroll
    for (int mi = 0; mi < 8; mi++) {
        int m = (mi < 4) ? (tm * 4 + mi) : (64 + tm * 4 + (mi - 4));
        float4 o = make_float4(acc[mi][0].x + bias[0], acc[mi][0].y + bias[1],
                               acc[mi][1].x + bias[2], acc[mi][1].y + bias[3]);
        *(float4*)&g_vp[((size_t)b * SYN + j0 + m) * 64 + n0] = o;
    }
}

// ---------------- K3: warp-autonomous flash attention -----------------------
// Each warp owns 8 query rows. QK/softmax/PV per warp need only __syncwarp.
// K/V tiles double-buffered via cp.async; ONE __syncthreads per j-tile.
__global__ __launch_bounds__(256, 2) void k3_attn() {
    extern __shared__ float smbuf[];
    float (*Qs)[SPAD] = (float(*)[SPAD])smbuf;        // [32][SPAD]   Q^T  [d][i]
    float (*Ks)[SPAD] = Qs + 32;                      // [2*32][SPAD] K^T  [buf][d][j]
    float (*Ss)[SPAD] = Ks + 64;                      // [64][SPAD]   S/P  [i][j] (warp-sliced)
    float (*Vs)[SPAD] = Ss + 64;                      // [2*64][SPAD] V    [buf][j][c]
    float* sm_f = (float*)(Vs + 128);                 // [64]
    float* sm_l = sm_f + 64;

    const int b  = blockIdx.y;
    const int i0 = blockIdx.x * 64;
    const int t  = threadIdx.x;
    const int w  = t >> 5, lane = t & 31;
    const float* qkb = g_qk + (size_t)b * SYN * 64;
    const float* vpb = g_vp + (size_t)b * SYN * 64;

    // thread mappings (all warp-local rows: warp w owns rows 8w..8w+7)
    const int Rq   = w * 8 + ((lane >> 4) << 2);   // QK/PV: 4 rows starting here
    const int tc   = lane & 15;                    // 4-col group (j in QK/P, c in PV)
    const int srow = w * 8 + ((lane >> 2) & 7);    // softmax row
    const int sq   = lane & 3;                     // softmax quarter

    // smem byte addresses for cp.async
    const unsigned smKs = (unsigned)__cvta_generic_to_shared(&Ks[0][0]);
    const unsigned smVs = (unsigned)__cvta_generic_to_shared(&Vs[0][0]);

    // Q load transposed (coalesced global, one-time)
#pragma unroll
    for (int u = 0; u < 8; u++) {
        int idx = t + 256 * u; int i = idx >> 5, d = idx & 31;
        Qs[d][i] = qkb[(size_t)(i0 + i) * 64 + d];
    }

    // cp.async tile issue: K (4B transposed) + V (16B rows)
    auto issue_tile = [&](int jt, int buf) {
        const int kd = lane;                 // d
        const float* ksrc = qkb + (size_t)jt * 64 * 64 + 32 + kd;
#pragma unroll
        for (int u = 0; u < 8; u++) {
            int j = w + 8 * u;
            cp_async4(smKs + ((buf * 32 + kd) * SPAD + j) * 4, ksrc + (size_t)j * 64);
        }
        const int vc4 = (t & 15) * 4;
        const float* vsrc = vpb + (size_t)jt * 64 * 64 + vc4;
#pragma unroll
        for (int u = 0; u < 4; u++) {
            int j = (t >> 4) + 16 * u;
            cp_async16(smVs + ((buf * 64 + j) * SPAD + vc4) * 4, vsrc + (size_t)j * 64);
        }
        cp_commit();
    };

    issue_tile(0, 0);
    cp_wait_all();
    __syncthreads();

    float m_i = -1e30f, l_i = 0.f;
    float2 acc[4][2];
#pragma unroll
    for (int r = 0; r < 4; r++) { acc[r][0] = make_float2(0.f, 0.f); acc[r][1] = make_float2(0.f, 0.f); }

    for (int jt = 0; jt < 32; jt++) {
        const int cur = jt & 1;
        if (jt + 1 < 32) issue_tile(jt + 1, cur ^ 1);

        // ---- QK^T (warp rows), 4x4 register tile ----
        float2 s2[4][2];
#pragma unroll
        for (int r = 0; r < 4; r++) { s2[r][0] = make_float2(0.f, 0.f); s2[r][1] = make_float2(0.f, 0.f); }
#pragma unroll
        for (int d = 0; d < 32; d++) {
            float4 q4 = *(const float4*)&Qs[d][Rq];
            float4 k4 = *(const float4*)&Ks[cur * 32 + d][tc * 4];
            float2 k01 = make_float2(k4.x, k4.y);
            float2 k23 = make_float2(k4.z, k4.w);
            float qa[4] = {q4.x, q4.y, q4.z, q4.w};
#pragma unroll
            for (int r = 0; r < 4; r++) {
                float2 qd = fdup(qa[r]);
                s2[r][0] = ffma2(qd, k01, s2[r][0]);
                s2[r][1] = ffma2(qd, k23, s2[r][1]);
            }
        }
#pragma unroll
        for (int r = 0; r < 4; r++) {
            float4 o = make_float4(s2[r][0].x, s2[r][0].y, s2[r][1].x, s2[r][1].y);
            *(float4*)&Ss[Rq + r][tc * 4] = o;
        }
        __syncwarp();

        // ---- online softmax (own row, quad shuffles) ----
        float4 pv[4];
        float mx = -1e30f;
#pragma unroll
        for (int u = 0; u < 4; u++) {
            pv[u] = *(const float4*)&Ss[srow][sq * 16 + u * 4];
            mx = fmaxf(mx, fmaxf(fmaxf(pv[u].x, pv[u].y), fmaxf(pv[u].z, pv[u].w)));
        }
        mx = fmaxf(mx, __shfl_xor_sync(0xFFFFFFFFu, mx, 1));
        mx = fmaxf(mx, __shfl_xor_sync(0xFFFFFFFFu, mx, 2));
        const float mnew = fmaxf(m_i, mx);
        const float fac  = __expf(m_i - mnew);
        float ssum = 0.f;
#pragma unroll
        for (int u = 0; u < 4; u++) {
            pv[u].x = __expf(pv[u].x - mnew);
            pv[u].y = __expf(pv[u].y - mnew);
            pv[u].z = __expf(pv[u].z - mnew);
            pv[u].w = __expf(pv[u].w - mnew);
            ssum += (pv[u].x + pv[u].y) + (pv[u].z + pv[u].w);
            *(float4*)&Ss[srow][sq * 16 + u * 4] = pv[u];
        }
        ssum += __shfl_xor_sync(0xFFFFFFFFu, ssum, 1);
        ssum += __shfl_xor_sync(0xFFFFFFFFu, ssum, 2);
        l_i = l_i * fac + ssum;
        m_i = mnew;
        if (sq == 0) { sm_f[srow] = fac; sm_l[srow] = l_i; }
        __syncwarp();

        // ---- PV accumulate (own rows, channels tc*4..+3) ----
        float fr[4];
#pragma unroll
        for (int r = 0; r < 4; r++) fr[r] = sm_f[Rq + r];
#pragma unroll
        for (int r = 0; r < 4; r++) {
            acc[r][0].x *= fr[r]; acc[r][0].y *= fr[r];
            acc[r][1].x *= fr[r]; acc[r][1].y *= fr[r];
        }
#pragma unroll
        for (int jg = 0; jg < 16; jg++) {
            float4 p4[4];
#pragma unroll
            for (int r = 0; r < 4; r++) p4[r] = *(const float4*)&Ss[Rq + r][jg * 4];
#pragma unroll
            for (int jj = 0; jj < 4; jj++) {
                float4 v4 = *(const float4*)&Vs[cur * 64 + jg * 4 + jj][tc * 4];
                float2 vlo = make_float2(v4.x, v4.y);
                float2 vhi = make_float2(v4.z, v4.w);
#pragma unroll
                for (int r = 0; r < 4; r++) {
                    float pj = (jj == 0) ? p4[r].x : (jj == 1) ? p4[r].y : (jj == 2) ? p4[r].z : p4[r].w;
                    float2 pd = fdup(pj);
                    acc[r][0] = ffma2(pd, vlo, acc[r][0]);
                    acc[r][1] = ffma2(pd, vhi, acc[r][1]);
                }
            }
        }

        if (jt + 1 < 32) cp_wait_all();
        __syncthreads();
    }

    // ---- epilogue: normalize, transpose via Ss, coalesced store ----
#pragma unroll
    for (int r = 0; r < 4; r++) {
        float il = 1.0f / sm_l[Rq + r];
        float4 o = make_float4(acc[r][0].x * il, acc[r][0].y * il,
                               acc[r][1].x * il, acc[r][1].y * il);
        *(float4*)&Ss[Rq + r][tc * 4] = o;   // Ss now holds O[i_local][c]
    }
    __syncthreads();
    float* ob = g_o + (size_t)b * 64 * SYN;
#pragma unroll
    for (int u = 0; u < 16; u++) {
        int id = t + 256 * u;            // 0..4095
        int c = id >> 6, il = id & 63;
        ob[(size_t)c * SYN + i0 + il] = Ss[il][c];
    }
}

// ---------------- K4: BN stats -> per-channel scale/shift -------------------
__global__ void k4_stats(const float* __restrict__ gamma,
                         const float* __restrict__ bn_w,
                         const float* __restrict__ bn_b) {
    __shared__ float rs[256], rq[256];
    const int c = blockIdx.x;
    const int t = threadIdx.x;
    float s = 0.f, s2 = 0.f;
    for (int b = 0; b < NB; b++) {
        const float* p = g_o + ((size_t)b * 64 + c) * SYN + t * 8;
#pragma unroll
        for (int u = 0; u < 2; u++) {
            float4 v = *(const float4*)(p + u * 4);
            s  += (v.x + v.y) + (v.z + v.w);
            s2 += (v.x * v.x + v.y * v.y) + (v.z * v.z + v.w * v.w);
        }
    }
    rs[t] = s; rq[t] = s2;
    __syncthreads();
    for (int st = 128; st > 0; st >>= 1) {
        if (t < st) { rs[t] += rs[t + st]; rq[t] += rq[t + st]; }
        __syncthreads();
    }
    if (t == 0) {
        const float N = 16384.f;
        float mean = rs[0] / N;
        float var  = rq[0] / N - mean * mean;
        float g = gamma[0];
        float inv = rsqrtf(g * g * var + 1e-5f);
        float sc = g * inv * bn_w[c];
        g_scale[c] = sc;
        g_shift[c] = bn_b[c] - mean * sc;
    }
}

// ---------------- K5: out = x + scale[c]*O[i>>2] + shift[c] ------------------
__global__ void k5_out(const float* __restrict__ x, float* __restrict__ out) {
    int idx = blockIdx.x * 256 + threadIdx.x;     // float4 index over out
    int c = (idx >> 11) & 63;
    float o = g_o[idx];
    float sc = g_scale[c], sh = g_shift[c];
    float add = fmaf(sc, o, sh);
    float4 xv = ((const float4*)x)[idx];
    float4 r = make_float4(xv.x + add, xv.y + add, xv.z + add, xv.w + add);
    ((float4*)out)[idx] = r;
}

// ---------------- launcher ---------------------------------------------------
extern "C" void kernel_launch(void* const* d_in, const int* in_sizes, int n_in,
                              void* d_out, int out_size) {
    const float* x     = (const float*)d_in[0];
    const float* y     = (const float*)d_in[1];
    const float* wq    = (const float*)d_in[2];
    const float* bq    = (const float*)d_in[3];
    const float* wk    = (const float*)d_in[4];
    const float* bk    = (const float*)d_in[5];
    const float* wv    = (const float*)d_in[6];
    const float* bv    = (const float*)d_in[7];
    const float* gamma = (const float*)d_in[8];
    const float* bn_w  = (const float*)d_in[9];
    const float* bn_b  = (const float*)d_in[10];
    float* out = (float*)d_out;

    const int k3_smem = (32 + 64 + 64 + 128) * SPAD * 4 + 2 * 64 * 4;  // 78848 B
    cudaFuncSetAttribute(k3_attn, cudaFuncAttributeMaxDynamicSharedMemorySize, k3_smem);

    k0_transpose<<<80, 256>>>(wq, wk, wv);
    k1_proj_qk<<<dim3(16, NB), 256>>>(y, bq, bk);
    k2_proj_v<<<dim3(16, NB), 256>>>(x, bv);
    k3_attn<<<dim3(32, NB), 256, k3_smem>>>();
    k4_stats<<<64, 256>>>(gamma, bn_w, bn_b);
    k5_out<<<4096, 256>>>(x, out);
}

// round 4
// speedup vs baseline: 1.3342x; 1.1460x over previous
#include <cuda_runtime.h>
#include <cuda_bf16.h>

#define NB   8
#define SXN  8192
#define CYC  256
#define SYN  2048
#define SPAD 68
#define QPAD 132

// ---------------- device scratch (no runtime allocation) -------------------
__device__ __align__(16) float g_wt [CYC * 64];              // [c][n] n<32: wq^T, n>=32: wk^T
__device__ __align__(16) float g_wvt[64 * 64];               // [c][n] = wv[n][c]
__device__ __align__(16) float g_qk [(size_t)NB * SYN * 64]; // [b][s][0:32]=q, [32:64]=k
__device__ __align__(16) float g_vp [(size_t)NB * SYN * 64]; // [b][j][c]
__device__ __align__(16) float g_o  [(size_t)NB * 64 * SYN]; // [b][c][i]
__device__ float g_scale[64];
__device__ float g_shift[64];

// ---------------- helpers ----------------------------------------------------
__device__ __forceinline__ float2 ffma2(float2 a, float2 b, float2 c) {
    unsigned long long ra = *reinterpret_cast<unsigned long long*>(&a);
    unsigned long long rb = *reinterpret_cast<unsigned long long*>(&b);
    unsigned long long rc = *reinterpret_cast<unsigned long long*>(&c);
    unsigned long long rd;
    asm("fma.rn.f32x2 %0, %1, %2, %3;" : "=l"(rd) : "l"(ra), "l"(rb), "l"(rc));
    return *reinterpret_cast<float2*>(&rd);
}
__device__ __forceinline__ float2 fdup(float x) { return make_float2(x, x); }

__device__ __forceinline__ void cp_async4(unsigned s, const float* g) {
    asm volatile("cp.async.ca.shared.global [%0], [%1], 4;" :: "r"(s), "l"(g));
}
__device__ __forceinline__ void cp_async16(unsigned s, const float* g) {
    asm volatile("cp.async.cg.shared.global [%0], [%1], 16;" :: "r"(s), "l"(g));
}
__device__ __forceinline__ void cp_commit() { asm volatile("cp.async.commit_group;"); }
__device__ __forceinline__ void cp_wait_all() { asm volatile("cp.async.wait_group 0;"); }

// ---------------- K0: weight transposes ------------------------------------
__global__ void k0_transpose(const float* __restrict__ wq,
                             const float* __restrict__ wk,
                             const float* __restrict__ wv) {
    int id = blockIdx.x * 256 + threadIdx.x;
    if (id < 16384) {
        int c = id & 255, n = id >> 8;
        g_wt[c * 64 + n] = (n < 32) ? wq[n * 256 + c] : wk[(n - 32) * 256 + c];
    } else if (id < 20480) {
        int i2 = id - 16384;
        int c = i2 & 63, n = i2 >> 6;
        g_wvt[c * 64 + n] = wv[n * 64 + c];
    }
}

// ---------------- K1: q/k projection GEMM ----------------------------------
__global__ __launch_bounds__(256) void k1_proj_qk(const float* __restrict__ y,
                                                  const float* __restrict__ bq,
                                                  const float* __restrict__ bk) {
    __shared__ __align__(16) float As[16][128];
    __shared__ __align__(16) float Bs[16][68];
    const int b  = blockIdx.y;
    const int s0 = blockIdx.x * 128;
    const int t  = threadIdx.x;
    const int tm = t & 15, tn = t >> 4;
    const int lk = t >> 4, lm = (t & 15) * 8;
    const int bn = t & 63, bk4 = t >> 6;
    float2 acc[8][2];
#pragma unroll
    for (int i = 0; i < 8; i++) { acc[i][0] = make_float2(0.f, 0.f); acc[i][1] = make_float2(0.f, 0.f); }
    const float* yb = y + (size_t)b * CYC * SYN + s0;

    for (int c0 = 0; c0 < CYC; c0 += 16) {
        float4 va = *(const float4*)(yb + (size_t)(c0 + lk) * SYN + lm);
        float4 vb = *(const float4*)(yb + (size_t)(c0 + lk) * SYN + lm + 4);
        float w4[4];
#pragma unroll
        for (int e = 0; e < 4; e++) w4[e] = g_wt[(size_t)(c0 + bk4 * 4 + e) * 64 + bn];
        __syncthreads();
        *(float4*)&As[lk][lm]     = va;
        *(float4*)&As[lk][lm + 4] = vb;
#pragma unroll
        for (int e = 0; e < 4; e++) Bs[bk4 * 4 + e][bn] = w4[e];
        __syncthreads();
#pragma unroll
        for (int k = 0; k < 16; k++) {
            float4 a0 = *(const float4*)&As[k][tm * 4];
            float4 a1 = *(const float4*)&As[k][64 + tm * 4];
            float4 bb = *(const float4*)&Bs[k][tn * 4];
            float2 b01 = make_float2(bb.x, bb.y);
            float2 b23 = make_float2(bb.z, bb.w);
            float am[8] = {a0.x, a0.y, a0.z, a0.w, a1.x, a1.y, a1.z, a1.w};
#pragma unroll
            for (int mi = 0; mi < 8; mi++) {
                float2 ad = fdup(am[mi]);
                acc[mi][0] = ffma2(ad, b01, acc[mi][0]);
                acc[mi][1] = ffma2(ad, b23, acc[mi][1]);
            }
        }
    }
    const int n0 = tn * 4;
    float bias[4];
#pragma unroll
    for (int e = 0; e < 4; e++) { int n = n0 + e; bias[e] = (n < 32) ? bq[n] : bk[n - 32]; }
#pragma unroll
    for (int mi = 0; mi < 8; mi++) {
        int m = (mi < 4) ? (tm * 4 + mi) : (64 + tm * 4 + (mi - 4));
        float4 o = make_float4(acc[mi][0].x + bias[0], acc[mi][0].y + bias[1],
                               acc[mi][1].x + bias[2], acc[mi][1].y + bias[3]);
        *(float4*)&g_qk[((size_t)b * SYN + s0 + m) * 64 + n0] = o;
    }
}

// ---------------- K2: pooled v projection GEMM ------------------------------
__global__ __launch_bounds__(256) void k2_proj_v(const float* __restrict__ x,
                                                 const float* __restrict__ bv) {
    __shared__ __align__(16) float As[16][128];
    __shared__ __align__(16) float Bs[16][68];
    const int b  = blockIdx.y;
    const int j0 = blockIdx.x * 128;
    const int t  = threadIdx.x;
    const int tm = t & 15, tn = t >> 4;
    const int lr = t >> 4;
    const int f4 = t & 15;
    const int bn = t & 63, bk4 = t >> 6;
    float2 acc[8][2];
#pragma unroll
    for (int i = 0; i < 8; i++) { acc[i][0] = make_float2(0.f, 0.f); acc[i][1] = make_float2(0.f, 0.f); }

    for (int c0 = 0; c0 < 64; c0 += 16) {
        const float* xb = x + ((size_t)b * 64 + c0 + lr) * SXN + (size_t)j0 * 4;
        float av[8];
#pragma unroll
        for (int e = 0; e < 8; e++) {
            float4 v = *(const float4*)(xb + (size_t)(f4 + 16 * e) * 4);
            av[e] = (v.x + v.y) + (v.z + v.w);
        }
        float w4[4];
#pragma unroll
        for (int e = 0; e < 4; e++) w4[e] = g_wvt[(size_t)(c0 + bk4 * 4 + e) * 64 + bn];
        __syncthreads();
#pragma unroll
        for (int e = 0; e < 8; e++) As[lr][f4 + 16 * e] = av[e];
#pragma unroll
        for (int e = 0; e < 4; e++) Bs[bk4 * 4 + e][bn] = w4[e];
        __syncthreads();
#pragma unroll
        for (int k = 0; k < 16; k++) {
            float4 a0 = *(const float4*)&As[k][tm * 4];
            float4 a1 = *(const float4*)&As[k][64 + tm * 4];
            float4 bb = *(const float4*)&Bs[k][tn * 4];
            float2 b01 = make_float2(bb.x, bb.y);
            float2 b23 = make_float2(bb.z, bb.w);
            float am[8] = {a0.x, a0.y, a0.z, a0.w, a1.x, a1.y, a1.z, a1.w};
#pragma unroll
            for (int mi = 0; mi < 8; mi++) {
                float2 ad = fdup(am[mi]);
                acc[mi][0] = ffma2(ad, b01, acc[mi][0]);
                acc[mi][1] = ffma2(ad, b23, acc[mi][1]);
            }
        }
    }
    const int n0 = tn * 4;
    float bias[4];
#pragma unroll
    for (int e = 0; e < 4; e++) bias[e] = 4.0f * bv[n0 + e];
#pragma unroll
    for (int mi = 0; mi < 8; mi++) {
        int m = (mi < 4) ? (tm * 4 + mi) : (64 + tm * 4 + (mi - 4));
        float4 o = make_float4(acc[mi][0].x + bias[0], acc[mi][0].y + bias[1],
                               acc[mi][1].x + bias[2], acc[mi][1].y + bias[3]);
        *(float4*)&g_vp[((size_t)b * SYN + j0 + m) * 64 + n0] = o;
    }
}

// ---------------- K3: flash attention, BM=128, register softmax -------------
// Warp w owns rows [16w,16w+16). Thread (rq=lane>>3, jg=lane&7):
//   rows = 16w + 4rq + r (r<4); QK j-cols / PV ch = {4jg..+3} u {32+4jg..+3}
__global__ __launch_bounds__(256, 1) void k3_attn() {
    extern __shared__ float smbuf[];
    float (*Qs)[QPAD] = (float(*)[QPAD])smbuf;            // [32][132]  Q^T [d][i]
    float (*Ks)[SPAD] = (float(*)[SPAD])(smbuf + 32 * QPAD); // [2*32][68] K^T [buf][d][j]
    float (*Vs)[SPAD] = Ks + 64;                          // [2*64][68] V [buf][j][c]
    float (*Ss)[SPAD] = Vs + 128;                         // [128][68]  P [i][j]

    const int b  = blockIdx.y;
    const int i0 = blockIdx.x * 128;
    const int t  = threadIdx.x;
    const int w  = t >> 5, lane = t & 31;
    const int rq = (lane >> 3) & 3, jg = lane & 7;
    const int rowbase = w * 16 + rq * 4;
    const float* qkb = g_qk + (size_t)b * SYN * 64;
    const float* vpb = g_vp + (size_t)b * SYN * 64;

    const unsigned smKs = (unsigned)__cvta_generic_to_shared(&Ks[0][0]);
    const unsigned smVs = (unsigned)__cvta_generic_to_shared(&Vs[0][0]);

    // Q load transposed: Qs[d][i], i 0..127
#pragma unroll
    for (int u = 0; u < 16; u++) {
        int idx = t + 256 * u; int i = idx >> 5, d = idx & 31;
        Qs[d][i] = qkb[(size_t)(i0 + i) * 64 + d];
    }

    auto issue_tile = [&](int jt, int buf) {
        const int kd = lane;
        const float* ksrc = qkb + (size_t)jt * 64 * 64 + 32 + kd;
#pragma unroll
        for (int u = 0; u < 8; u++) {
            int j = w + 8 * u;
            cp_async4(smKs + ((buf * 32 + kd) * SPAD + j) * 4, ksrc + (size_t)j * 64);
        }
        const int vc4 = (t & 15) * 4;
        const float* vsrc = vpb + (size_t)jt * 64 * 64 + vc4;
#pragma unroll
        for (int u = 0; u < 4; u++) {
            int j = (t >> 4) + 16 * u;
            cp_async16(smVs + ((buf * 64 + j) * SPAD + vc4) * 4, vsrc + (size_t)j * 64);
        }
        cp_commit();
    };

    issue_tile(0, 0);
    cp_wait_all();
    __syncthreads();

    float m_i[4], l_i[4];
    float2 acc[4][4];
#pragma unroll
    for (int r = 0; r < 4; r++) {
        m_i[r] = -1e30f; l_i[r] = 0.f;
#pragma unroll
        for (int h = 0; h < 4; h++) acc[r][h] = make_float2(0.f, 0.f);
    }

    for (int jt = 0; jt < 32; jt++) {
        const int cur = jt & 1;
        if (jt + 1 < 32) issue_tile(jt + 1, cur ^ 1);

        // ---- QK^T: 4 rows x 8 j (cols 4jg..+3 and 32+4jg..+3) ----
        float2 s2[4][4];
#pragma unroll
        for (int r = 0; r < 4; r++)
#pragma unroll
            for (int h = 0; h < 4; h++) s2[r][h] = make_float2(0.f, 0.f);
#pragma unroll
        for (int d = 0; d < 32; d++) {
            float4 q4 = *(const float4*)&Qs[d][rowbase];
            const float* kr = &Ks[cur * 32 + d][0];
            float4 kA = *(const float4*)&kr[4 * jg];
            float4 kB = *(const float4*)&kr[32 + 4 * jg];
            float2 a01 = make_float2(kA.x, kA.y), a23 = make_float2(kA.z, kA.w);
            float2 b01 = make_float2(kB.x, kB.y), b23 = make_float2(kB.z, kB.w);
            float qa[4] = {q4.x, q4.y, q4.z, q4.w};
#pragma unroll
            for (int r = 0; r < 4; r++) {
                float2 qd = fdup(qa[r]);
                s2[r][0] = ffma2(qd, a01, s2[r][0]);
                s2[r][1] = ffma2(qd, a23, s2[r][1]);
                s2[r][2] = ffma2(qd, b01, s2[r][2]);
                s2[r][3] = ffma2(qd, b23, s2[r][3]);
            }
        }

        // ---- register softmax (butterfly over jg lanes) ----
        float fac[4];
#pragma unroll
        for (int r = 0; r < 4; r++) {
            float mx = fmaxf(fmaxf(fmaxf(s2[r][0].x, s2[r][0].y), fmaxf(s2[r][1].x, s2[r][1].y)),
                             fmaxf(fmaxf(s2[r][2].x, s2[r][2].y), fmaxf(s2[r][3].x, s2[r][3].y)));
            mx = fmaxf(mx, __shfl_xor_sync(0xFFFFFFFFu, mx, 1));
            mx = fmaxf(mx, __shfl_xor_sync(0xFFFFFFFFu, mx, 2));
            mx = fmaxf(mx, __shfl_xor_sync(0xFFFFFFFFu, mx, 4));
            float mnew = fmaxf(m_i[r], mx);
            fac[r] = __expf(m_i[r] - mnew);
            m_i[r] = mnew;
            float sum = 0.f;
#pragma unroll
            for (int h = 0; h < 4; h++) {
                s2[r][h].x = __expf(s2[r][h].x - mnew);
                s2[r][h].y = __expf(s2[r][h].y - mnew);
                sum += s2[r][h].x + s2[r][h].y;
            }
            sum += __shfl_xor_sync(0xFFFFFFFFu, sum, 1);
            sum += __shfl_xor_sync(0xFFFFFFFFu, sum, 2);
            sum += __shfl_xor_sync(0xFFFFFFFFu, sum, 4);
            l_i[r] = l_i[r] * fac[r] + sum;
            // store P (once)
            *(float4*)&Ss[rowbase + r][4 * jg] =
                make_float4(s2[r][0].x, s2[r][0].y, s2[r][1].x, s2[r][1].y);
            *(float4*)&Ss[rowbase + r][32 + 4 * jg] =
                make_float4(s2[r][2].x, s2[r][2].y, s2[r][3].x, s2[r][3].y);
        }
        __syncwarp();

        // ---- PV: rows rowbase..+3, channels {4jg..+3, 32+4jg..+3} ----
#pragma unroll
        for (int r = 0; r < 4; r++) {
            float f = fac[r];
#pragma unroll
            for (int h = 0; h < 4; h++) { acc[r][h].x *= f; acc[r][h].y *= f; }
        }
#pragma unroll
        for (int jgx = 0; jgx < 16; jgx++) {
            float4 pr[4];
#pragma unroll
            for (int r = 0; r < 4; r++) pr[r] = *(const float4*)&Ss[rowbase + r][jgx * 4];
#pragma unroll
            for (int jj = 0; jj < 4; jj++) {
                int j = jgx * 4 + jj;
                const float* vr = &Vs[cur * 64 + j][0];
                float4 vA = *(const float4*)&vr[4 * jg];
                float4 vB = *(const float4*)&vr[32 + 4 * jg];
                float2 vA01 = make_float2(vA.x, vA.y), vA23 = make_float2(vA.z, vA.w);
                float2 vB01 = make_float2(vB.x, vB.y), vB23 = make_float2(vB.z, vB.w);
#pragma unroll
                for (int r = 0; r < 4; r++) {
                    float pj = (jj == 0) ? pr[r].x : (jj == 1) ? pr[r].y : (jj == 2) ? pr[r].z : pr[r].w;
                    float2 pd = fdup(pj);
                    acc[r][0] = ffma2(pd, vA01, acc[r][0]);
                    acc[r][1] = ffma2(pd, vA23, acc[r][1]);
                    acc[r][2] = ffma2(pd, vB01, acc[r][2]);
                    acc[r][3] = ffma2(pd, vB23, acc[r][3]);
                }
            }
        }

        if (jt + 1 < 32) cp_wait_all();
        __syncthreads();
    }

    // ---- epilogue: normalize, stage in Ss, coalesced transpose store ----
#pragma unroll
    for (int r = 0; r < 4; r++) {
        float il = 1.0f / l_i[r];
        *(float4*)&Ss[rowbase + r][4 * jg] =
            make_float4(acc[r][0].x * il, acc[r][0].y * il, acc[r][1].x * il, acc[r][1].y * il);
        *(float4*)&Ss[rowbase + r][32 + 4 * jg] =
            make_float4(acc[r][2].x * il, acc[r][2].y * il, acc[r][3].x * il, acc[r][3].y * il);
    }
    __syncthreads();
    float* ob = g_o + (size_t)b * 64 * SYN;
#pragma unroll
    for (int u = 0; u < 32; u++) {
        int id = t + 256 * u;            // 0..8191
        int c = id >> 7, il = id & 127;
        ob[(size_t)c * SYN + i0 + il] = Ss[il][c];
    }
}

// ---------------- K4: BN stats -> per-channel scale/shift -------------------
__global__ void k4_stats(const float* __restrict__ gamma,
                         const float* __restrict__ bn_w,
                         const float* __restrict__ bn_b) {
    __shared__ float rs[256], rq[256];
    const int c = blockIdx.x;
    const int t = threadIdx.x;
    float s = 0.f, s2 = 0.f;
    for (int b = 0; b < NB; b++) {
        const float* p = g_o + ((size_t)b * 64 + c) * SYN + t * 8;
#pragma unroll
        for (int u = 0; u < 2; u++) {
            float4 v = *(const float4*)(p + u * 4);
            s  += (v.x + v.y) + (v.z + v.w);
            s2 += (v.x * v.x + v.y * v.y) + (v.z * v.z + v.w * v.w);
        }
    }
    rs[t] = s; rq[t] = s2;
    __syncthreads();
    for (int st = 128; st > 0; st >>= 1) {
        if (t < st) { rs[t] += rs[t + st]; rq[t] += rq[t + st]; }
        __syncthreads();
    }
    if (t == 0) {
        const float N = 16384.f;
        float mean = rs[0] / N;
        float var  = rq[0] / N - mean * mean;
        float g = gamma[0];
        float inv = rsqrtf(g * g * var + 1e-5f);
        float sc = g * inv * bn_w[c];
        g_scale[c] = sc;
        g_shift[c] = bn_b[c] - mean * sc;
    }
}

// ---------------- K5: out = x + scale[c]*O[i>>2] + shift[c] ------------------
__global__ void k5_out(const float* __restrict__ x, float* __restrict__ out) {
    int idx = blockIdx.x * 256 + threadIdx.x;     // float4 index over out
    int c = (idx >> 11) & 63;
    float o = g_o[idx];
    float sc = g_scale[c], sh = g_shift[c];
    float add = fmaf(sc, o, sh);
    float4 xv = ((const float4*)x)[idx];
    float4 r = make_float4(xv.x + add, xv.y + add, xv.z + add, xv.w + add);
    ((float4*)out)[idx] = r;
}

// ---------------- launcher ---------------------------------------------------
extern "C" void kernel_launch(void* const* d_in, const int* in_sizes, int n_in,
                              void* d_out, int out_size) {
    const float* x     = (const float*)d_in[0];
    const float* y     = (const float*)d_in[1];
    const float* wq    = (const float*)d_in[2];
    const float* bq    = (const float*)d_in[3];
    const float* wk    = (const float*)d_in[4];
    const float* bk    = (const float*)d_in[5];
    const float* wv    = (const float*)d_in[6];
    const float* bv    = (const float*)d_in[7];
    const float* gamma = (const float*)d_in[8];
    const float* bn_w  = (const float*)d_in[9];
    const float* bn_b  = (const float*)d_in[10];
    float* out = (float*)d_out;

    // Qs 32*132 + Ks 64*68 + Vs 128*68 + Ss 128*68 floats
    const int k3_smem = (32 * QPAD + (64 + 128 + 128) * SPAD) * 4;  // 103936 B
    cudaFuncSetAttribute(k3_attn, cudaFuncAttributeMaxDynamicSharedMemorySize, k3_smem);

    k0_transpose<<<80, 256>>>(wq, wk, wv);
    k1_proj_qk<<<dim3(16, NB), 256>>>(y, bq, bk);
    k2_proj_v<<<dim3(16, NB), 256>>>(x, bv);
    k3_attn<<<dim3(16, NB), 256, k3_smem>>>();
    k4_stats<<<64, 256>>>(gamma, bn_w, bn_b);
    k5_out<<<4096, 256>>>(x, out);
}

// round 5
// speedup vs baseline: 1.3365x; 1.0017x over previous
#include <cuda_runtime.h>
#include <cuda_bf16.h>

#define NB   8
#define SXN  8192
#define CYC  256
#define SYN  2048
#define SPAD 68
#define QPAD 132

// ---------------- device scratch (no runtime allocation) -------------------
__device__ __align__(16) float g_wt [CYC * 64];              // [c][n] n<32: wq^T, n>=32: wk^T
__device__ __align__(16) float g_wvt[64 * 64];               // [c][n] = wv[n][c]
__device__ __align__(16) float g_qk [(size_t)NB * SYN * 64]; // [b][s][0:32]=q, [32:64]=k
__device__ __align__(16) float g_vp [(size_t)NB * SYN * 64]; // [b][j][c]
__device__ __align__(16) float g_o  [(size_t)NB * 64 * SYN]; // [b][c][i]
__device__ float g_scale[64];
__device__ float g_shift[64];

// ---------------- helpers ----------------------------------------------------
__device__ __forceinline__ float2 ffma2(float2 a, float2 b, float2 c) {
    unsigned long long ra = *reinterpret_cast<unsigned long long*>(&a);
    unsigned long long rb = *reinterpret_cast<unsigned long long*>(&b);
    unsigned long long rc = *reinterpret_cast<unsigned long long*>(&c);
    unsigned long long rd;
    asm("fma.rn.f32x2 %0, %1, %2, %3;" : "=l"(rd) : "l"(ra), "l"(rb), "l"(rc));
    return *reinterpret_cast<float2*>(&rd);
}
__device__ __forceinline__ float2 fdup(float x) { return make_float2(x, x); }

__device__ __forceinline__ void cp_async4(unsigned s, const float* g) {
    asm volatile("cp.async.ca.shared.global [%0], [%1], 4;" :: "r"(s), "l"(g));
}
__device__ __forceinline__ void cp_async16(unsigned s, const float* g) {
    asm volatile("cp.async.cg.shared.global [%0], [%1], 16;" :: "r"(s), "l"(g));
}
__device__ __forceinline__ void cp_commit() { asm volatile("cp.async.commit_group;"); }
__device__ __forceinline__ void cp_wait_all() { asm volatile("cp.async.wait_group 0;"); }

// ---------------- K0: weight transposes ------------------------------------
__global__ void k0_transpose(const float* __restrict__ wq,
                             const float* __restrict__ wk,
                             const float* __restrict__ wv) {
    int id = blockIdx.x * 256 + threadIdx.x;
    if (id < 16384) {
        int c = id & 255, n = id >> 8;
        g_wt[c * 64 + n] = (n < 32) ? wq[n * 256 + c] : wk[(n - 32) * 256 + c];
    } else if (id < 20480) {
        int i2 = id - 16384;
        int c = i2 & 63, n = i2 >> 6;
        g_wvt[c * 64 + n] = wv[n * 64 + c];
    }
}

// ---------------- K1: q/k projection GEMM ----------------------------------
__global__ __launch_bounds__(256) void k1_proj_qk(const float* __restrict__ y,
                                                  const float* __restrict__ bq,
                                                  const float* __restrict__ bk) {
    __shared__ __align__(16) float As[16][128];
    __shared__ __align__(16) float Bs[16][68];
    const int b  = blockIdx.y;
    const int s0 = blockIdx.x * 128;
    const int t  = threadIdx.x;
    const int tm = t & 15, tn = t >> 4;
    const int lk = t >> 4, lm = (t & 15) * 8;
    const int bn = t & 63, bk4 = t >> 6;
    float2 acc[8][2];
#pragma unroll
    for (int i = 0; i < 8; i++) { acc[i][0] = make_float2(0.f, 0.f); acc[i][1] = make_float2(0.f, 0.f); }
    const float* yb = y + (size_t)b * CYC * SYN + s0;

    for (int c0 = 0; c0 < CYC; c0 += 16) {
        float4 va = *(const float4*)(yb + (size_t)(c0 + lk) * SYN + lm);
        float4 vb = *(const float4*)(yb + (size_t)(c0 + lk) * SYN + lm + 4);
        float w4[4];
#pragma unroll
        for (int e = 0; e < 4; e++) w4[e] = g_wt[(size_t)(c0 + bk4 * 4 + e) * 64 + bn];
        __syncthreads();
        *(float4*)&As[lk][lm]     = va;
        *(float4*)&As[lk][lm + 4] = vb;
#pragma unroll
        for (int e = 0; e < 4; e++) Bs[bk4 * 4 + e][bn] = w4[e];
        __syncthreads();
#pragma unroll
        for (int k = 0; k < 16; k++) {
            float4 a0 = *(const float4*)&As[k][tm * 4];
            float4 a1 = *(const float4*)&As[k][64 + tm * 4];
            float4 bb = *(const float4*)&Bs[k][tn * 4];
            float2 b01 = make_float2(bb.x, bb.y);
            float2 b23 = make_float2(bb.z, bb.w);
            float am[8] = {a0.x, a0.y, a0.z, a0.w, a1.x, a1.y, a1.z, a1.w};
#pragma unroll
            for (int mi = 0; mi < 8; mi++) {
                float2 ad = fdup(am[mi]);
                acc[mi][0] = ffma2(ad, b01, acc[mi][0]);
                acc[mi][1] = ffma2(ad, b23, acc[mi][1]);
            }
        }
    }
    const int n0 = tn * 4;
    float bias[4];
#pragma unroll
    for (int e = 0; e < 4; e++) { int n = n0 + e; bias[e] = (n < 32) ? bq[n] : bk[n - 32]; }
#pragma unroll
    for (int mi = 0; mi < 8; mi++) {
        int m = (mi < 4) ? (tm * 4 + mi) : (64 + tm * 4 + (mi - 4));
        float4 o = make_float4(acc[mi][0].x + bias[0], acc[mi][0].y + bias[1],
                               acc[mi][1].x + bias[2], acc[mi][1].y + bias[3]);
        *(float4*)&g_qk[((size_t)b * SYN + s0 + m) * 64 + n0] = o;
    }
}

// ---------------- K2: pooled v projection GEMM ------------------------------
__global__ __launch_bounds__(256) void k2_proj_v(const float* __restrict__ x,
                                                 const float* __restrict__ bv) {
    __shared__ __align__(16) float As[16][128];
    __shared__ __align__(16) float Bs[16][68];
    const int b  = blockIdx.y;
    const int j0 = blockIdx.x * 128;
    const int t  = threadIdx.x;
    const int tm = t & 15, tn = t >> 4;
    const int lr = t >> 4;
    const int f4 = t & 15;
    const int bn = t & 63, bk4 = t >> 6;
    float2 acc[8][2];
#pragma unroll
    for (int i = 0; i < 8; i++) { acc[i][0] = make_float2(0.f, 0.f); acc[i][1] = make_float2(0.f, 0.f); }

    for (int c0 = 0; c0 < 64; c0 += 16) {
        const float* xb = x + ((size_t)b * 64 + c0 + lr) * SXN + (size_t)j0 * 4;
        float av[8];
#pragma unroll
        for (int e = 0; e < 8; e++) {
            float4 v = *(const float4*)(xb + (size_t)(f4 + 16 * e) * 4);
            av[e] = (v.x + v.y) + (v.z + v.w);
        }
        float w4[4];
#pragma unroll
        for (int e = 0; e < 4; e++) w4[e] = g_wvt[(size_t)(c0 + bk4 * 4 + e) * 64 + bn];
        __syncthreads();
#pragma unroll
        for (int e = 0; e < 8; e++) As[lr][f4 + 16 * e] = av[e];
#pragma unroll
        for (int e = 0; e < 4; e++) Bs[bk4 * 4 + e][bn] = w4[e];
        __syncthreads();
#pragma unroll
        for (int k = 0; k < 16; k++) {
            float4 a0 = *(const float4*)&As[k][tm * 4];
            float4 a1 = *(const float4*)&As[k][64 + tm * 4];
            float4 bb = *(const float4*)&Bs[k][tn * 4];
            float2 b01 = make_float2(bb.x, bb.y);
            float2 b23 = make_float2(bb.z, bb.w);
            float am[8] = {a0.x, a0.y, a0.z, a0.w, a1.x, a1.y, a1.z, a1.w};
#pragma unroll
            for (int mi = 0; mi < 8; mi++) {
                float2 ad = fdup(am[mi]);
                acc[mi][0] = ffma2(ad, b01, acc[mi][0]);
                acc[mi][1] = ffma2(ad, b23, acc[mi][1]);
            }
        }
    }
    const int n0 = tn * 4;
    float bias[4];
#pragma unroll
    for (int e = 0; e < 4; e++) bias[e] = 4.0f * bv[n0 + e];
#pragma unroll
    for (int mi = 0; mi < 8; mi++) {
        int m = (mi < 4) ? (tm * 4 + mi) : (64 + tm * 4 + (mi - 4));
        float4 o = make_float4(acc[mi][0].x + bias[0], acc[mi][0].y + bias[1],
                               acc[mi][1].x + bias[2], acc[mi][1].y + bias[3]);
        *(float4*)&g_vp[((size_t)b * SYN + j0 + m) * 64 + n0] = o;
    }
}

// ---------------- K3: flash attention, BM=128, register softmax -------------
// Warp w owns rows [16w,16w+16). Thread (rq=lane>>3, jg=lane&7):
//   rows = 16w + 4rq + r (r<4); QK j-cols / PV ch = {4jg..+3} u {32+4jg..+3}
__global__ __launch_bounds__(256, 1) void k3_attn() {
    extern __shared__ float smbuf[];
    float (*Qs)[QPAD] = (float(*)[QPAD])smbuf;            // [32][132]  Q^T [d][i]
    float (*Ks)[SPAD] = (float(*)[SPAD])(smbuf + 32 * QPAD); // [2*32][68] K^T [buf][d][j]
    float (*Vs)[SPAD] = Ks + 64;                          // [2*64][68] V [buf][j][c]
    float (*Ss)[SPAD] = Vs + 128;                         // [128][68]  P [i][j]

    const int b  = blockIdx.y;
    const int i0 = blockIdx.x * 128;
    const int t  = threadIdx.x;
    const int w  = t >> 5, lane = t & 31;
    const int rq = (lane >> 3) & 3, jg = lane & 7;
    const int rowbase = w * 16 + rq * 4;
    const float* qkb = g_qk + (size_t)b * SYN * 64;
    const float* vpb = g_vp + (size_t)b * SYN * 64;

    const unsigned smKs = (unsigned)__cvta_generic_to_shared(&Ks[0][0]);
    const unsigned smVs = (unsigned)__cvta_generic_to_shared(&Vs[0][0]);

    // Q load transposed: Qs[d][i], i 0..127
#pragma unroll
    for (int u = 0; u < 16; u++) {
        int idx = t + 256 * u; int i = idx >> 5, d = idx & 31;
        Qs[d][i] = qkb[(size_t)(i0 + i) * 64 + d];
    }

    auto issue_tile = [&](int jt, int buf) {
        const int kd = lane;
        const float* ksrc = qkb + (size_t)jt * 64 * 64 + 32 + kd;
#pragma unroll
        for (int u = 0; u < 8; u++) {
            int j = w + 8 * u;
            cp_async4(smKs + ((buf * 32 + kd) * SPAD + j) * 4, ksrc + (size_t)j * 64);
        }
        const int vc4 = (t & 15) * 4;
        const float* vsrc = vpb + (size_t)jt * 64 * 64 + vc4;
#pragma unroll
        for (int u = 0; u < 4; u++) {
            int j = (t >> 4) + 16 * u;
            cp_async16(smVs + ((buf * 64 + j) * SPAD + vc4) * 4, vsrc + (size_t)j * 64);
        }
        cp_commit();
    };

    issue_tile(0, 0);
    cp_wait_all();
    __syncthreads();

    float m_i[4], l_i[4];
    float2 acc[4][4];
#pragma unroll
    for (int r = 0; r < 4; r++) {
        m_i[r] = -1e30f; l_i[r] = 0.f;
#pragma unroll
        for (int h = 0; h < 4; h++) acc[r][h] = make_float2(0.f, 0.f);
    }

    for (int jt = 0; jt < 32; jt++) {
        const int cur = jt & 1;
        if (jt + 1 < 32) issue_tile(jt + 1, cur ^ 1);

        // ---- QK^T: 4 rows x 8 j (cols 4jg..+3 and 32+4jg..+3) ----
        float2 s2[4][4];
#pragma unroll
        for (int r = 0; r < 4; r++)
#pragma unroll
            for (int h = 0; h < 4; h++) s2[r][h] = make_float2(0.f, 0.f);
#pragma unroll
        for (int d = 0; d < 32; d++) {
            float4 q4 = *(const float4*)&Qs[d][rowbase];
            const float* kr = &Ks[cur * 32 + d][0];
            float4 kA = *(const float4*)&kr[4 * jg];
            float4 kB = *(const float4*)&kr[32 + 4 * jg];
            float2 a01 = make_float2(kA.x, kA.y), a23 = make_float2(kA.z, kA.w);
            float2 b01 = make_float2(kB.x, kB.y), b23 = make_float2(kB.z, kB.w);
            float qa[4] = {q4.x, q4.y, q4.z, q4.w};
#pragma unroll
            for (int r = 0; r < 4; r++) {
                float2 qd = fdup(qa[r]);
                s2[r][0] = ffma2(qd, a01, s2[r][0]);
                s2[r][1] = ffma2(qd, a23, s2[r][1]);
                s2[r][2] = ffma2(qd, b01, s2[r][2]);
                s2[r][3] = ffma2(qd, b23, s2[r][3]);
            }
        }

        // ---- register softmax (butterfly over jg lanes) ----
        float fac[4];
#pragma unroll
        for (int r = 0; r < 4; r++) {
            float mx = fmaxf(fmaxf(fmaxf(s2[r][0].x, s2[r][0].y), fmaxf(s2[r][1].x, s2[r][1].y)),
                             fmaxf(fmaxf(s2[r][2].x, s2[r][2].y), fmaxf(s2[r][3].x, s2[r][3].y)));
            mx = fmaxf(mx, __shfl_xor_sync(0xFFFFFFFFu, mx, 1));
            mx = fmaxf(mx, __shfl_xor_sync(0xFFFFFFFFu, mx, 2));
            mx = fmaxf(mx, __shfl_xor_sync(0xFFFFFFFFu, mx, 4));
            float mnew = fmaxf(m_i[r], mx);
            fac[r] = __expf(m_i[r] - mnew);
            m_i[r] = mnew;
            float sum = 0.f;
#pragma unroll
            for (int h = 0; h < 4; h++) {
                s2[r][h].x = __expf(s2[r][h].x - mnew);
                s2[r][h].y = __expf(s2[r][h].y - mnew);
                sum += s2[r][h].x + s2[r][h].y;
            }
            sum += __shfl_xor_sync(0xFFFFFFFFu, sum, 1);
            sum += __shfl_xor_sync(0xFFFFFFFFu, sum, 2);
            sum += __shfl_xor_sync(0xFFFFFFFFu, sum, 4);
            l_i[r] = l_i[r] * fac[r] + sum;
            // store P (once)
            *(float4*)&Ss[rowbase + r][4 * jg] =
                make_float4(s2[r][0].x, s2[r][0].y, s2[r][1].x, s2[r][1].y);
            *(float4*)&Ss[rowbase + r][32 + 4 * jg] =
                make_float4(s2[r][2].x, s2[r][2].y, s2[r][3].x, s2[r][3].y);
        }
        __syncwarp();

        // ---- PV: rows rowbase..+3, channels {4jg..+3, 32+4jg..+3} ----
#pragma unroll
        for (int r = 0; r < 4; r++) {
            float f = fac[r];
#pragma unroll
            for (int h = 0; h < 4; h++) { acc[r][h].x *= f; acc[r][h].y *= f; }
        }
#pragma unroll
        for (int jgx = 0; jgx < 16; jgx++) {
            float4 pr[4];
#pragma unroll
            for (int r = 0; r < 4; r++) pr[r] = *(const float4*)&Ss[rowbase + r][jgx * 4];
#pragma unroll
            for (int jj = 0; jj < 4; jj++) {
                int j = jgx * 4 + jj;
                const float* vr = &Vs[cur * 64 + j][0];
                float4 vA = *(const float4*)&vr[4 * jg];
                float4 vB = *(const float4*)&vr[32 + 4 * jg];
                float2 vA01 = make_float2(vA.x, vA.y), vA23 = make_float2(vA.z, vA.w);
                float2 vB01 = make_float2(vB.x, vB.y), vB23 = make_float2(vB.z, vB.w);
#pragma unroll
                for (int r = 0; r < 4; r++) {
                    float pj = (jj == 0) ? pr[r].x : (jj == 1) ? pr[r].y : (jj == 2) ? pr[r].z : pr[r].w;
                    float2 pd = fdup(pj);
                    acc[r][0] = ffma2(pd, vA01, acc[r][0]);
                    acc[r][1] = ffma2(pd, vA23, acc[r][1]);
                    acc[r][2] = ffma2(pd, vB01, acc[r][2]);
                    acc[r][3] = ffma2(pd, vB23, acc[r][3]);
                }
            }
        }

        if (jt + 1 < 32) cp_wait_all();
        __syncthreads();
    }

    // ---- epilogue: normalize, stage in Ss, coalesced transpose store ----
#pragma unroll
    for (int r = 0; r < 4; r++) {
        float il = 1.0f / l_i[r];
        *(float4*)&Ss[rowbase + r][4 * jg] =
            make_float4(acc[r][0].x * il, acc[r][0].y * il, acc[r][1].x * il, acc[r][1].y * il);
        *(float4*)&Ss[rowbase + r][32 + 4 * jg] =
            make_float4(acc[r][2].x * il, acc[r][2].y * il, acc[r][3].x * il, acc[r][3].y * il);
    }
    __syncthreads();
    float* ob = g_o + (size_t)b * 64 * SYN;
#pragma unroll
    for (int u = 0; u < 32; u++) {
        int id = t + 256 * u;            // 0..8191
        int c = id >> 7, il = id & 127;
        ob[(size_t)c * SYN + i0 + il] = Ss[il][c];
    }
}

// ---------------- K4: BN stats -> per-channel scale/shift -------------------
__global__ void k4_stats(const float* __restrict__ gamma,
                         const float* __restrict__ bn_w,
                         const float* __restrict__ bn_b) {
    __shared__ float rs[256], rq[256];
    const int c = blockIdx.x;
    const int t = threadIdx.x;
    float s = 0.f, s2 = 0.f;
    for (int b = 0; b < NB; b++) {
        const float* p = g_o + ((size_t)b * 64 + c) * SYN + t * 8;
#pragma unroll
        for (int u = 0; u < 2; u++) {
            float4 v = *(const float4*)(p + u * 4);
            s  += (v.x + v.y) + (v.z + v.w);
            s2 += (v.x * v.x + v.y * v.y) + (v.z * v.z + v.w * v.w);
        }
    }
    rs[t] = s; rq[t] = s2;
    __syncthreads();
    for (int st = 128; st > 0; st >>= 1) {
        if (t < st) { rs[t] += rs[t + st]; rq[t] += rq[t + st]; }
        __syncthreads();
    }
    if (t == 0) {
        const float N = 16384.f;
        float mean = rs[0] / N;
        float var  = rq[0] / N - mean * mean;
        float g = gamma[0];
        float inv = rsqrtf(g * g * var + 1e-5f);
        float sc = g * inv * bn_w[c];
        g_scale[c] = sc;
        g_shift[c] = bn_b[c] - mean * sc;
    }
}

// ---------------- K5: out = x + scale[c]*O[i>>2] + shift[c] ------------------
__global__ void k5_out(const float* __restrict__ x, float* __restrict__ out) {
    int idx = blockIdx.x * 256 + threadIdx.x;     // float4 index over out
    int c = (idx >> 11) & 63;
    float o = g_o[idx];
    float sc = g_scale[c], sh = g_shift[c];
    float add = fmaf(sc, o, sh);
    float4 xv = ((const float4*)x)[idx];
    float4 r = make_float4(xv.x + add, xv.y + add, xv.z + add, xv.w + add);
    ((float4*)out)[idx] = r;
}

// ---------------- launcher ---------------------------------------------------
extern "C" void kernel_launch(void* const* d_in, const int* in_sizes, int n_in,
                              void* d_out, int out_size) {
    const float* x     = (const float*)d_in[0];
    const float* y     = (const float*)d_in[1];
    const float* wq    = (const float*)d_in[2];
    const float* bq    = (const float*)d_in[3];
    const float* wk    = (const float*)d_in[4];
    const float* bk    = (const float*)d_in[5];
    const float* wv    = (const float*)d_in[6];
    const float* bv    = (const float*)d_in[7];
    const float* gamma = (const float*)d_in[8];
    const float* bn_w  = (const float*)d_in[9];
    const float* bn_b  = (const float*)d_in[10];
    float* out = (float*)d_out;

    // Qs 32*132 + Ks 64*68 + Vs 128*68 + Ss 128*68 floats
    const int k3_smem = (32 * QPAD + (64 + 128 + 128) * SPAD) * 4;  // 103936 B
    cudaFuncSetAttribute(k3_attn, cudaFuncAttributeMaxDynamicSharedMemorySize, k3_smem);

    k0_transpose<<<80, 256>>>(wq, wk, wv);
    k1_proj_qk<<<dim3(16, NB), 256>>>(y, bq, bk);
    k2_proj_v<<<dim3(16, NB), 256>>>(x, bv);
    k3_attn<<<dim3(16, NB), 256, k3_smem>>>();
    k4_stats<<<64, 256>>>(gamma, bn_w, bn_b);
    k5_out<<<4096, 256>>>(x, out);
}

// round 7
// speedup vs baseline: 1.8727x; 1.4011x over previous
#include <cuda_runtime.h>
#include <cuda_bf16.h>

#define NB   8
#define SXN  8192
#define CYC  256
#define SYN  2048
#define SPAD 68
#define QPAD 132

__device__ __align__(16) float g_wt [CYC * 64];
__device__ __align__(16) float g_wvt[64 * 64];
__device__ __align__(16) float g_qk [(size_t)NB * SYN * 64];
// V^T tiles bf16: [b][jt][ hi: 64x64 | lo: 64x64 ] row-major [j][c]
__device__ __align__(16) unsigned short g_vt[(size_t)NB * 32 * 8192];
__device__ __align__(16) float g_o  [(size_t)NB * 64 * SYN];
__device__ float g_scale[64];
__device__ float g_shift[64];

__device__ __forceinline__ float2 ffma2(float2 a, float2 b, float2 c) {
    unsigned long long ra = *reinterpret_cast<unsigned long long*>(&a);
    unsigned long long rb = *reinterpret_cast<unsigned long long*>(&b);
    unsigned long long rc = *reinterpret_cast<unsigned long long*>(&c);
    unsigned long long rd;
    asm("fma.rn.f32x2 %0, %1, %2, %3;" : "=l"(rd) : "l"(ra), "l"(rb), "l"(rc));
    return *reinterpret_cast<float2*>(&rd);
}
__device__ __forceinline__ float2 fdup(float x) { return make_float2(x, x); }
__device__ __forceinline__ void cp_async4(unsigned s, const void* g) {
    asm volatile("cp.async.ca.shared.global [%0], [%1], 4;" :: "r"(s), "l"(g));
}
__device__ __forceinline__ void cp_async16(unsigned s, const void* g) {
    asm volatile("cp.async.cg.shared.global [%0], [%1], 16;" :: "r"(s), "l"(g));
}
#define CP_COMMIT() asm volatile("cp.async.commit_group;")
#define CP_WAIT(n)  asm volatile("cp.async.wait_group %0;" :: "n"(n))
__device__ __forceinline__ unsigned smem_u32(const void* p) {
    unsigned a;
    asm("{ .reg .u64 t; cvta.to.shared.u64 t, %1; cvt.u32.u64 %0, t; }" : "=r"(a) : "l"(p));
    return a;
}
#define CVTBF2(r, a, b) asm("cvt.rn.satfinite.bf16x2.f32 %0, %1, %2;" : "=r"(r) : "f"(b), "f"(a))
#define LDSM4(r, addr) asm volatile( \
    "ldmatrix.sync.aligned.m8n8.x4.shared.b16 {%0,%1,%2,%3}, [%4];" \
    : "=r"((r)[0]), "=r"((r)[1]), "=r"((r)[2]), "=r"((r)[3]) : "r"(addr))
#define LDSM4T(r, addr) asm volatile( \
    "ldmatrix.sync.aligned.m8n8.x4.trans.shared.b16 {%0,%1,%2,%3}, [%4];" \
    : "=r"((r)[0]), "=r"((r)[1]), "=r"((r)[2]), "=r"((r)[3]) : "r"(addr))
#define MMA16816(d, a, b0, b1) asm volatile( \
    "mma.sync.aligned.m16n8k16.row.col.f32.bf16.bf16.f32 " \
    "{%0,%1,%2,%3}, {%4,%5,%6,%7}, {%8,%9}, {%0,%1,%2,%3};" \
    : "+f"((d)[0]), "+f"((d)[1]), "+f"((d)[2]), "+f"((d)[3]) \
    : "r"((a)[0]), "r"((a)[1]), "r"((a)[2]), "r"((a)[3]), "r"(b0), "r"(b1))

__device__ __forceinline__ unsigned short f2bf(float v) {
    __nv_bfloat16 h = __float2bfloat16(v);
    return *reinterpret_cast<unsigned short*>(&h);
}
__device__ __forceinline__ float bfhi(unsigned short h) {
    return __uint_as_float((unsigned)h << 16);
}

// ---------------- K0 ----------------
__global__ void k0_transpose(const float* __restrict__ wq, const float* __restrict__ wk,
                             const float* __restrict__ wv) {
    int id = blockIdx.x * 256 + threadIdx.x;
    if (id < 16384) {
        int c = id & 255, n = id >> 8;
        g_wt[c * 64 + n] = (n < 32) ? wq[n * 256 + c] : wk[(n - 32) * 256 + c];
    } else if (id < 20480) {
        int i2 = id - 16384, c = i2 & 63, n = i2 >> 6;
        g_wvt[c * 64 + n] = wv[n * 64 + c];
    }
}

// ---------------- K1: q/k projection ----------------
__global__ __launch_bounds__(256) void k1_proj_qk(const float* __restrict__ y,
                                                  const float* __restrict__ bq,
                                                  const float* __restrict__ bk) {
    __shared__ __align__(16) float As[16][128];
    __shared__ __align__(16) float Bs[16][68];
    const int b = blockIdx.y, s0 = blockIdx.x * 128, t = threadIdx.x;
    const int tm = t & 15, tn = t >> 4;
    const int lk = t >> 4, lm = (t & 15) * 8;
    const int bn = t & 63, bk4 = t >> 6;
    float2 acc[8][2];
#pragma unroll
    for (int i = 0; i < 8; i++) { acc[i][0] = make_float2(0.f,0.f); acc[i][1] = make_float2(0.f,0.f); }
    const float* yb = y + (size_t)b * CYC * SYN + s0;
    for (int c0 = 0; c0 < CYC; c0 += 16) {
        float4 va = *(const float4*)(yb + (size_t)(c0 + lk) * SYN + lm);
        float4 vb = *(const float4*)(yb + (size_t)(c0 + lk) * SYN + lm + 4);
        float w4[4];
#pragma unroll
        for (int e = 0; e < 4; e++) w4[e] = g_wt[(size_t)(c0 + bk4 * 4 + e) * 64 + bn];
        __syncthreads();
        *(float4*)&As[lk][lm] = va; *(float4*)&As[lk][lm + 4] = vb;
#pragma unroll
        for (int e = 0; e < 4; e++) Bs[bk4 * 4 + e][bn] = w4[e];
        __syncthreads();
#pragma unroll
        for (int k = 0; k < 16; k++) {
            float4 a0 = *(const float4*)&As[k][tm * 4];
            float4 a1 = *(const float4*)&As[k][64 + tm * 4];
            float4 bb = *(const float4*)&Bs[k][tn * 4];
            float2 b01 = make_float2(bb.x, bb.y), b23 = make_float2(bb.z, bb.w);
            float am[8] = {a0.x, a0.y, a0.z, a0.w, a1.x, a1.y, a1.z, a1.w};
#pragma unroll
            for (int mi = 0; mi < 8; mi++) {
                float2 ad = fdup(am[mi]);
                acc[mi][0] = ffma2(ad, b01, acc[mi][0]);
                acc[mi][1] = ffma2(ad, b23, acc[mi][1]);
            }
        }
    }
    const int n0 = tn * 4;
    float bias[4];
#pragma unroll
    for (int e = 0; e < 4; e++) { int n = n0 + e; bias[e] = (n < 32) ? bq[n] : bk[n - 32]; }
#pragma unroll
    for (int mi = 0; mi < 8; mi++) {
        int m = (mi < 4) ? (tm * 4 + mi) : (64 + tm * 4 + (mi - 4));
        *(float4*)&g_qk[((size_t)b * SYN + s0 + m) * 64 + n0] =
            make_float4(acc[mi][0].x + bias[0], acc[mi][0].y + bias[1],
                        acc[mi][1].x + bias[2], acc[mi][1].y + bias[3]);
    }
}

// ---------------- K2: pooled v proj -> bf16 hi/lo V tiles -------------------
__global__ __launch_bounds__(256) void k2_proj_v(const float* __restrict__ x,
                                                 const float* __restrict__ bv) {
    __shared__ __align__(16) float As[16][128];
    __shared__ __align__(16) float Bs[16][68];
    const int b = blockIdx.y, j0 = blockIdx.x * 128, t = threadIdx.x;
    const int tm = t & 15, tn = t >> 4;
    const int lr = t >> 4, f4 = t & 15;
    const int bn = t & 63, bk4 = t >> 6;
    float2 acc[8][2];
#pragma unroll
    for (int i = 0; i < 8; i++) { acc[i][0] = make_float2(0.f,0.f); acc[i][1] = make_float2(0.f,0.f); }
    for (int c0 = 0; c0 < 64; c0 += 16) {
        const float* xb = x + ((size_t)b * 64 + c0 + lr) * SXN + (size_t)j0 * 4;
        float av[8];
#pragma unroll
        for (int e = 0; e < 8; e++) {
            float4 v = *(const float4*)(xb + (size_t)(f4 + 16 * e) * 4);
            av[e] = (v.x + v.y) + (v.z + v.w);
        }
        float w4[4];
#pragma unroll
        for (int e = 0; e < 4; e++) w4[e] = g_wvt[(size_t)(c0 + bk4 * 4 + e) * 64 + bn];
        __syncthreads();
#pragma unroll
        for (int e = 0; e < 8; e++) As[lr][f4 + 16 * e] = av[e];
#pragma unroll
        for (int e = 0; e < 4; e++) Bs[bk4 * 4 + e][bn] = w4[e];
        __syncthreads();
#pragma unroll
        for (int k = 0; k < 16; k++) {
            float4 a0 = *(const float4*)&As[k][tm * 4];
            float4 a1 = *(const float4*)&As[k][64 + tm * 4];
            float4 bb = *(const float4*)&Bs[k][tn * 4];
            float2 b01 = make_float2(bb.x, bb.y), b23 = make_float2(bb.z, bb.w);
            float am[8] = {a0.x, a0.y, a0.z, a0.w, a1.x, a1.y, a1.z, a1.w};
#pragma unroll
            for (int mi = 0; mi < 8; mi++) {
                float2 ad = fdup(am[mi]);
                acc[mi][0] = ffma2(ad, b01, acc[mi][0]);
                acc[mi][1] = ffma2(ad, b23, acc[mi][1]);
            }
        }
    }
    const int n0 = tn * 4;
    float bias[4];
#pragma unroll
    for (int e = 0; e < 4; e++) bias[e] = 4.0f * bv[n0 + e];
#pragma unroll
    for (int mi = 0; mi < 8; mi++) {
        int m = (mi < 4) ? (tm * 4 + mi) : (64 + tm * 4 + (mi - 4));
        int jt = blockIdx.x * 2 + (m >> 6), jl = m & 63;
        size_t be = (size_t)(b * 32 + jt) * 8192;
        float v0 = acc[mi][0].x + bias[0], v1 = acc[mi][0].y + bias[1];
        float v2 = acc[mi][1].x + bias[2], v3 = acc[mi][1].y + bias[3];
        unsigned short h0 = f2bf(v0), h1 = f2bf(v1), h2 = f2bf(v2), h3 = f2bf(v3);
        *(ushort4*)&g_vt[be + jl * 64 + n0] = make_ushort4(h0, h1, h2, h3);
        *(ushort4*)&g_vt[be + 4096 + jl * 64 + n0] = make_ushort4(
            f2bf(v0 - bfhi(h0)), f2bf(v1 - bfhi(h1)),
            f2bf(v2 - bfhi(h2)), f2bf(v3 - bfhi(h3)));
    }
}

// ---------------- K3: SIMT QK + HMMA PV ----------------
#define QS_OFF 0
#define KS_OFF 16896
#define VS_OFF 34304
#define VBUF   18432
#define PS_OFF 71168
#define PHALF  18432
#define SL_OFF 108032
#define K3_SMEM 108544

__global__ __launch_bounds__(256, 1) void k3_attn() {
    extern __shared__ char sm[];
    const unsigned smb = smem_u32(sm);
    float* qs  = (float*)(sm + QS_OFF);
    float* ksm = (float*)(sm + KS_OFF);
    float* slm = (float*)(sm + SL_OFF);
    float* osm = (float*)(sm + PS_OFF);   // aliased after MMA finishes

    const int b = blockIdx.y, i0 = blockIdx.x * 128, t = threadIdx.x;
    const int w = t >> 5, lane = t & 31;
    const int rq = (lane >> 3) & 3, jg = lane & 7;
    const int rowbase = w * 16 + rq * 4;
    const float* qkb = g_qk + (size_t)b * SYN * 64;

#pragma unroll
    for (int u = 0; u < 16; u++) {
        int idx = t + 256 * u, i = idx >> 5, d = idx & 31;
        qs[d * QPAD + i] = qkb[(size_t)(i0 + i) * 64 + d];
    }
    auto issue_K = [&](int jt, int buf) {
        const float* ksrc = qkb + (size_t)jt * 4096 + 32 + lane;
#pragma unroll
        for (int u = 0; u < 8; u++) {
            int j = w + 8 * u;
            cp_async4(smb + KS_OFF + (((unsigned)(buf * 32 + lane)) * SPAD + j) * 4,
                      ksrc + (size_t)j * 64);
        }
    };
    auto issue_V = [&](int jt) {
        const char* src = (const char*)g_vt + (size_t)(b * 32 + jt) * 16384;
        unsigned dst = smb + VS_OFF + (unsigned)(jt & 1) * VBUF;
#pragma unroll
        for (int u = 0; u < 4; u++) {
            int ch = t + 256 * u;
            cp_async16(dst + (unsigned)(ch >> 3) * 144 + (unsigned)(ch & 7) * 16,
                       src + (size_t)ch * 16);
        }
    };
    issue_K(0, 0); issue_V(0); CP_COMMIT();
    CP_WAIT(0);
    __syncthreads();

    float l_i[4] = {0.f, 0.f, 0.f, 0.f};
    float acc[8][4];
#pragma unroll
    for (int n = 0; n < 8; n++)
#pragma unroll
        for (int e = 0; e < 4; e++) acc[n][e] = 0.f;

    const unsigned phb = smb + PS_OFF, plb = phb + PHALF;
    const unsigned arow = (unsigned)(w * 16 + (lane & 15)) * 144 + (unsigned)(lane >> 4) * 16;
    const unsigned brow = (unsigned)(lane & 15) * 144 + (unsigned)(lane >> 4) * 16;

    for (int jt = 0; jt < 32; jt++) {
        const int cur = jt & 1;
        if (jt + 1 < 32) { issue_K(jt + 1, cur ^ 1); issue_V(jt + 1); CP_COMMIT(); }

        // ---- QK^T fp32 ----
        float2 s2[4][4];
#pragma unroll
        for (int r = 0; r < 4; r++)
#pragma unroll
            for (int h = 0; h < 4; h++) s2[r][h] = make_float2(0.f, 0.f);
#pragma unroll
        for (int d = 0; d < 32; d++) {
            float4 q4 = *(const float4*)&qs[d * QPAD + rowbase];
            const float* kr = &ksm[(cur * 32 + d) * SPAD];
            float4 kA = *(const float4*)&kr[4 * jg];
            float4 kB = *(const float4*)&kr[32 + 4 * jg];
            float2 a01 = make_float2(kA.x, kA.y), a23 = make_float2(kA.z, kA.w);
            float2 b01 = make_float2(kB.x, kB.y), b23 = make_float2(kB.z, kB.w);
            float qa[4] = {q4.x, q4.y, q4.z, q4.w};
#pragma unroll
            for (int r = 0; r < 4; r++) {
                float2 qd = fdup(qa[r]);
                s2[r][0] = ffma2(qd, a01, s2[r][0]);
                s2[r][1] = ffma2(qd, a23, s2[r][1]);
                s2[r][2] = ffma2(qd, b01, s2[r][2]);
                s2[r][3] = ffma2(qd, b23, s2[r][3]);
            }
        }
        // ---- exp (max-free) + l, P store bf16 hi/lo ----
#pragma unroll
        for (int r = 0; r < 4; r++) {
            float sum = 0.f;
#pragma unroll
            for (int h = 0; h < 4; h++) {
                s2[r][h].x = __expf(s2[r][h].x);
                s2[r][h].y = __expf(s2[r][h].y);
                sum += s2[r][h].x + s2[r][h].y;
            }
            sum += __shfl_xor_sync(0xFFFFFFFFu, sum, 1);
            sum += __shfl_xor_sync(0xFFFFFFFFu, sum, 2);
            sum += __shfl_xor_sync(0xFFFFFFFFu, sum, 4);
            l_i[r] += sum;
            unsigned ro = (unsigned)(rowbase + r) * 144 + 8u * jg;
            unsigned h0, h1, h2, h3;
            CVTBF2(h0, s2[r][0].x, s2[r][0].y);
            CVTBF2(h1, s2[r][1].x, s2[r][1].y);
            CVTBF2(h2, s2[r][2].x, s2[r][2].y);
            CVTBF2(h3, s2[r][3].x, s2[r][3].y);
            unsigned q0, q1, q2, q3;
            CVTBF2(q0, s2[r][0].x - __uint_as_float(h0 << 16),
                       s2[r][0].y - __uint_as_float(h0 & 0xFFFF0000u));
            CVTBF2(q1, s2[r][1].x - __uint_as_float(h1 << 16),
                       s2[r][1].y - __uint_as_float(h1 & 0xFFFF0000u));
            CVTBF2(q2, s2[r][2].x - __uint_as_float(h2 << 16),
                       s2[r][2].y - __uint_as_float(h2 & 0xFFFF0000u));
            CVTBF2(q3, s2[r][3].x - __uint_as_float(h3 << 16),
                       s2[r][3].y - __uint_as_float(h3 & 0xFFFF0000u));
            *(uint2*)(sm + PS_OFF + ro)        = make_uint2(h0, h1);
            *(uint2*)(sm + PS_OFF + ro + 64)   = make_uint2(h2, h3);
            *(uint2*)(sm + PS_OFF + PHALF + ro)      = make_uint2(q0, q1);
            *(uint2*)(sm + PS_OFF + PHALF + ro + 64) = make_uint2(q2, q3);
        }
        __syncwarp();

        // ---- PV on HMMA: warp rows 16w..16w+15, all 64 channels ----
        const unsigned vhb = smb + VS_OFF + (unsigned)cur * VBUF;
        const unsigned vlb = vhb + 64u * 144u;
#pragma unroll
        for (int kk = 0; kk < 4; kk++) {
            unsigned ao = arow + (unsigned)kk * 32;
            unsigned ah[4], al[4];
            LDSM4(ah, phb + ao);
            LDSM4(al, plb + ao);
            unsigned bo = brow + (unsigned)kk * 2304;
#pragma unroll
            for (int np = 0; np < 4; np++) {
                unsigned bb = bo + (unsigned)np * 32;
                unsigned bh[4], bl[4];
                LDSM4T(bh, vhb + bb);
                LDSM4T(bl, vlb + bb);
                MMA16816(acc[2*np],     ah, bh[0], bh[1]);
                MMA16816(acc[2*np],     ah, bl[0], bl[1]);
                MMA16816(acc[2*np],     al, bh[0], bh[1]);
                MMA16816(acc[2*np + 1], ah, bh[2], bh[3]);
                MMA16816(acc[2*np + 1], ah, bl[2], bl[3]);
                MMA16816(acc[2*np + 1], al, bh[2], bh[3]);
            }
        }
        if (jt + 1 < 32) CP_WAIT(0);
        __syncthreads();
    }

    // ---- epilogue ----
    if (jg == 0) {
#pragma unroll
        for (int r = 0; r < 4; r++) slm[rowbase + r] = l_i[r];
    }
    __syncthreads();
    const int rlo = w * 16 + (lane >> 2), rhi = rlo + 8;
    const float il0 = 1.0f / slm[rlo], il1 = 1.0f / slm[rhi];
#pragma unroll
    for (int nt = 0; nt < 8; nt++) {
        int c = nt * 8 + (lane & 3) * 2;
        osm[rlo * 68 + c]     = acc[nt][0] * il0;
        osm[rlo * 68 + c + 1] = acc[nt][1] * il0;
        osm[rhi * 68 + c]     = acc[nt][2] * il1;
        osm[rhi * 68 + c + 1] = acc[nt][3] * il1;
    }
    __syncthreads();
    float* ob = g_o + (size_t)b * 64 * SYN;
#pragma unroll
    for (int u = 0; u < 32; u++) {
        int id = t + 256 * u, c = id >> 7, il = id & 127;
        ob[(size_t)c * SYN + i0 + il] = osm[il * 68 + c];
    }
}

// ---------------- K4 ----------------
__global__ void k4_stats(const float* __restrict__ gamma, const float* __restrict__ bn_w,
                         const float* __restrict__ bn_b) {
    __shared__ float rs[256], rq[256];
    const int c = blockIdx.x, t = threadIdx.x;
    float s = 0.f, s2 = 0.f;
    for (int b = 0; b < NB; b++) {
        const float* p = g_o + ((size_t)b * 64 + c) * SYN + t * 8;
#pragma unroll
        for (int u = 0; u < 2; u++) {
            float4 v = *(const float4*)(p + u * 4);
            s += (v.x + v.y) + (v.z + v.w);
            s2 += (v.x*v.x + v.y*v.y) + (v.z*v.z + v.w*v.w);
        }
    }
    rs[t] = s; rq[t] = s2;
    __syncthreads();
    for (int st = 128; st > 0; st >>= 1) {
        if (t < st) { rs[t] += rs[t + st]; rq[t] += rq[t + st]; }
        __syncthreads();
    }
    if (t == 0) {
        const float N = 16384.f;
        float mean = rs[0] / N, var = rq[0] / N - mean * mean;
        float g = gamma[0];
        float inv = rsqrtf(g * g * var + 1e-5f);
        float sc = g * inv * bn_w[c];
        g_scale[c] = sc;
        g_shift[c] = bn_b[c] - mean * sc;
    }
}

// ---------------- K5 ----------------
__global__ void k5_out(const float* __restrict__ x, float* __restrict__ out) {
    int idx = blockIdx.x * 256 + threadIdx.x;
    int c = (idx >> 11) & 63;
    float add = fmaf(g_scale[c], g_o[idx], g_shift[c]);
    float4 xv = ((const float4*)x)[idx];
    ((float4*)out)[idx] = make_float4(xv.x + add, xv.y + add, xv.z + add, xv.w + add);
}

// ---------------- launcher ----------------
extern "C" void kernel_launch(void* const* d_in, const int* in_sizes, int n_in,
                              void* d_out, int out_size) {
    const float* x     = (const float*)d_in[0];
    const float* y     = (const float*)d_in[1];
    const float* wq    = (const float*)d_in[2];
    const float* bq    = (const float*)d_in[3];
    const float* wk    = (const float*)d_in[4];
    const float* bk    = (const float*)d_in[5];
    const float* wv    = (const float*)d_in[6];
    const float* bv    = (const float*)d_in[7];
    const float* gamma = (const float*)d_in[8];
    const float* bn_w  = (const float*)d_in[9];
    const float* bn_b  = (const float*)d_in[10];
    float* out = (float*)d_out;

    cudaFuncSetAttribute(k3_attn, cudaFuncAttributeMaxDynamicSharedMemorySize, K3_SMEM);
    k0_transpose<<<80, 256>>>(wq, wk, wv);
    k1_proj_qk<<<dim3(16, NB), 256>>>(y, bq, bk);
    k2_proj_v<<<dim3(16, NB), 256>>>(x, bv);
    k3_attn<<<dim3(16, NB), 256, K3_SMEM>>>();
    k4_stats<<<64, 256>>>(gamma, bn_w, bn_b);
    k5_out<<<4096, 256>>>(x, out);
}

// round 8
// speedup vs baseline: 2.3732x; 1.2673x over previous
#include <cuda_runtime.h>
#include <cuda_bf16.h>

#define NB 8
#define SXN 8192
#define CYC 256
#define SYN 2048

__device__ __align__(16) float g_wt[CYC * 64];
__device__ __align__(16) float g_wvt[64 * 64];
__device__ __align__(16) unsigned short g_qh[(size_t)NB * SYN * 64]; // [s][0:32 q|32:64 k] hi
__device__ __align__(16) unsigned short g_ql[(size_t)NB * SYN * 64]; // lo
__device__ __align__(16) unsigned short g_vt[(size_t)NB * 32 * 8192]; // [b][jt][hi 64x64|lo 64x64]
__device__ __align__(16) float g_o[(size_t)NB * 64 * SYN];
__device__ float g_scale[64];
__device__ float g_shift[64];

__device__ __forceinline__ float2 ffma2(float2 a, float2 b, float2 c) {
    unsigned long long ra = *reinterpret_cast<unsigned long long*>(&a);
    unsigned long long rb = *reinterpret_cast<unsigned long long*>(&b);
    unsigned long long rc = *reinterpret_cast<unsigned long long*>(&c);
    unsigned long long rd;
    asm("fma.rn.f32x2 %0, %1, %2, %3;" : "=l"(rd) : "l"(ra), "l"(rb), "l"(rc));
    return *reinterpret_cast<float2*>(&rd);
}
__device__ __forceinline__ float2 fdup(float x) { return make_float2(x, x); }
__device__ __forceinline__ void cp_async16(unsigned s, const void* g) {
    asm volatile("cp.async.cg.shared.global [%0], [%1], 16;" :: "r"(s), "l"(g));
}
#define CP_COMMIT() asm volatile("cp.async.commit_group;")
#define CP_WAIT(n)  asm volatile("cp.async.wait_group %0;" :: "n"(n))
__device__ __forceinline__ unsigned smem_u32(const void* p) {
    unsigned a;
    asm("{ .reg .u64 t; cvta.to.shared.u64 t, %1; cvt.u32.u64 %0, t; }" : "=r"(a) : "l"(p));
    return a;
}
#define CVTBF2(r, a, b) asm("cvt.rn.satfinite.bf16x2.f32 %0, %1, %2;" : "=r"(r) : "f"(b), "f"(a))
#define LDSM4(r, addr) asm volatile( \
    "ldmatrix.sync.aligned.m8n8.x4.shared.b16 {%0,%1,%2,%3}, [%4];" \
    : "=r"((r)[0]), "=r"((r)[1]), "=r"((r)[2]), "=r"((r)[3]) : "r"(addr))
#define LDSM4T(r, addr) asm volatile( \
    "ldmatrix.sync.aligned.m8n8.x4.trans.shared.b16 {%0,%1,%2,%3}, [%4];" \
    : "=r"((r)[0]), "=r"((r)[1]), "=r"((r)[2]), "=r"((r)[3]) : "r"(addr))
#define MMA16816(d, a, b0, b1) asm volatile( \
    "mma.sync.aligned.m16n8k16.row.col.f32.bf16.bf16.f32 " \
    "{%0,%1,%2,%3}, {%4,%5,%6,%7}, {%8,%9}, {%0,%1,%2,%3};" \
    : "+f"((d)[0]), "+f"((d)[1]), "+f"((d)[2]), "+f"((d)[3]) \
    : "r"((a)[0]), "r"((a)[1]), "r"((a)[2]), "r"((a)[3]), "r"(b0), "r"(b1))

__device__ __forceinline__ unsigned short f2bf(float v) {
    __nv_bfloat16 h = __float2bfloat16(v);
    return *reinterpret_cast<unsigned short*>(&h);
}
__device__ __forceinline__ float bfhi(unsigned short h) {
    return __uint_as_float((unsigned)h << 16);
}

// ---------------- K0 ----------------
__global__ void k0_transpose(const float* __restrict__ wq, const float* __restrict__ wk,
                             const float* __restrict__ wv) {
    int id = blockIdx.x * 256 + threadIdx.x;
    if (id < 16384) {
        int c = id & 255, n = id >> 8;
        g_wt[c * 64 + n] = (n < 32) ? wq[n * 256 + c] : wk[(n - 32) * 256 + c];
    } else if (id < 20480) {
        int i2 = id - 16384, c = i2 & 63, n = i2 >> 6;
        g_wvt[c * 64 + n] = wv[n * 64 + c];
    }
}

// ---------------- K1: q/k projection -> bf16 hi/lo ----------------
__global__ __launch_bounds__(256) void k1_proj_qk(const float* __restrict__ y,
                                                  const float* __restrict__ bq,
                                                  const float* __restrict__ bk) {
    __shared__ __align__(16) float As[16][128];
    __shared__ __align__(16) float Bs[16][68];
    const int b = blockIdx.y, s0 = blockIdx.x * 128, t = threadIdx.x;
    const int tm = t & 15, tn = t >> 4;
    const int lk = t >> 4, lm = (t & 15) * 8;
    const int bn = t & 63, bk4 = t >> 6;
    float2 acc[8][2];
#pragma unroll
    for (int i = 0; i < 8; i++) { acc[i][0] = make_float2(0.f,0.f); acc[i][1] = make_float2(0.f,0.f); }
    const float* yb = y + (size_t)b * CYC * SYN + s0;
    for (int c0 = 0; c0 < CYC; c0 += 16) {
        float4 va = *(const float4*)(yb + (size_t)(c0 + lk) * SYN + lm);
        float4 vb = *(const float4*)(yb + (size_t)(c0 + lk) * SYN + lm + 4);
        float w4[4];
#pragma unroll
        for (int e = 0; e < 4; e++) w4[e] = g_wt[(size_t)(c0 + bk4 * 4 + e) * 64 + bn];
        __syncthreads();
        *(float4*)&As[lk][lm] = va; *(float4*)&As[lk][lm + 4] = vb;
#pragma unroll
        for (int e = 0; e < 4; e++) Bs[bk4 * 4 + e][bn] = w4[e];
        __syncthreads();
#pragma unroll
        for (int k = 0; k < 16; k++) {
            float4 a0 = *(const float4*)&As[k][tm * 4];
            float4 a1 = *(const float4*)&As[k][64 + tm * 4];
            float4 bb = *(const float4*)&Bs[k][tn * 4];
            float2 b01 = make_float2(bb.x, bb.y), b23 = make_float2(bb.z, bb.w);
            float am[8] = {a0.x, a0.y, a0.z, a0.w, a1.x, a1.y, a1.z, a1.w};
#pragma unroll
            for (int mi = 0; mi < 8; mi++) {
                float2 ad = fdup(am[mi]);
                acc[mi][0] = ffma2(ad, b01, acc[mi][0]);
                acc[mi][1] = ffma2(ad, b23, acc[mi][1]);
            }
        }
    }
    const int n0 = tn * 4;
    float bias[4];
#pragma unroll
    for (int e = 0; e < 4; e++) { int n = n0 + e; bias[e] = (n < 32) ? bq[n] : bk[n - 32]; }
#pragma unroll
    for (int mi = 0; mi < 8; mi++) {
        int m = (mi < 4) ? (tm * 4 + mi) : (64 + tm * 4 + (mi - 4));
        float v0 = acc[mi][0].x + bias[0], v1 = acc[mi][0].y + bias[1];
        float v2 = acc[mi][1].x + bias[2], v3 = acc[mi][1].y + bias[3];
        unsigned short h0 = f2bf(v0), h1 = f2bf(v1), h2 = f2bf(v2), h3 = f2bf(v3);
        size_t o = ((size_t)b * SYN + s0 + m) * 64 + n0;
        *(ushort4*)&g_qh[o] = make_ushort4(h0, h1, h2, h3);
        *(ushort4*)&g_ql[o] = make_ushort4(
            f2bf(v0 - bfhi(h0)), f2bf(v1 - bfhi(h1)),
            f2bf(v2 - bfhi(h2)), f2bf(v3 - bfhi(h3)));
    }
}

// ---------------- K2: pooled v proj -> bf16 hi/lo V tiles -------------------
__global__ __launch_bounds__(256) void k2_proj_v(const float* __restrict__ x,
                                                 const float* __restrict__ bv) {
    __shared__ __align__(16) float As[16][128];
    __shared__ __align__(16) float Bs[16][68];
    const int b = blockIdx.y, j0 = blockIdx.x * 128, t = threadIdx.x;
    const int tm = t & 15, tn = t >> 4;
    const int lr = t >> 4, f4 = t & 15;
    const int bn = t & 63, bk4 = t >> 6;
    float2 acc[8][2];
#pragma unroll
    for (int i = 0; i < 8; i++) { acc[i][0] = make_float2(0.f,0.f); acc[i][1] = make_float2(0.f,0.f); }
    for (int c0 = 0; c0 < 64; c0 += 16) {
        const float* xb = x + ((size_t)b * 64 + c0 + lr) * SXN + (size_t)j0 * 4;
        float av[8];
#pragma unroll
        for (int e = 0; e < 8; e++) {
            float4 v = *(const float4*)(xb + (size_t)(f4 + 16 * e) * 4);
            av[e] = (v.x + v.y) + (v.z + v.w);
        }
        float w4[4];
#pragma unroll
        for (int e = 0; e < 4; e++) w4[e] = g_wvt[(size_t)(c0 + bk4 * 4 + e) * 64 + bn];
        __syncthreads();
#pragma unroll
        for (int e = 0; e < 8; e++) As[lr][f4 + 16 * e] = av[e];
#pragma unroll
        for (int e = 0; e < 4; e++) Bs[bk4 * 4 + e][bn] = w4[e];
        __syncthreads();
#pragma unroll
        for (int k = 0; k < 16; k++) {
            float4 a0 = *(const float4*)&As[k][tm * 4];
            float4 a1 = *(const float4*)&As[k][64 + tm * 4];
            float4 bb = *(const float4*)&Bs[k][tn * 4];
            float2 b01 = make_float2(bb.x, bb.y), b23 = make_float2(bb.z, bb.w);
            float am[8] = {a0.x, a0.y, a0.z, a0.w, a1.x, a1.y, a1.z, a1.w};
#pragma unroll
            for (int mi = 0; mi < 8; mi++) {
                float2 ad = fdup(am[mi]);
                acc[mi][0] = ffma2(ad, b01, acc[mi][0]);
                acc[mi][1] = ffma2(ad, b23, acc[mi][1]);
            }
        }
    }
    const int n0 = tn * 4;
    float bias[4];
#pragma unroll
    for (int e = 0; e < 4; e++) bias[e] = 4.0f * bv[n0 + e];
#pragma unroll
    for (int mi = 0; mi < 8; mi++) {
        int m = (mi < 4) ? (tm * 4 + mi) : (64 + tm * 4 + (mi - 4));
        int jt = blockIdx.x * 2 + (m >> 6), jl = m & 63;
        size_t be = (size_t)(b * 32 + jt) * 8192;
        float v0 = acc[mi][0].x + bias[0], v1 = acc[mi][0].y + bias[1];
        float v2 = acc[mi][1].x + bias[2], v3 = acc[mi][1].y + bias[3];
        unsigned short h0 = f2bf(v0), h1 = f2bf(v1), h2 = f2bf(v2), h3 = f2bf(v3);
        *(ushort4*)&g_vt[be + jl * 64 + n0] = make_ushort4(h0, h1, h2, h3);
        *(ushort4*)&g_vt[be + 4096 + jl * 64 + n0] = make_ushort4(
            f2bf(v0 - bfhi(h0)), f2bf(v1 - bfhi(h1)),
            f2bf(v2 - bfhi(h2)), f2bf(v3 - bfhi(h3)));
    }
}

// ---------------- K3: full HMMA attention ----------------
// smem: P[hi 0..16K | lo 16K..32K] (128B rows, XOR16 swizzle)
//       K 32768 (buf*10240, lo +5120, rows 80B)  V 53248 (buf*18432, rows 144B)
//       slm 90112
#define K3_SMEM 90624

__global__ __launch_bounds__(256, 1) void k3_attn() {
    extern __shared__ char sm[];
    const unsigned smb = smem_u32(sm);
    float* slm = (float*)(sm + 90112);
    float* osm = (float*)sm;
    const int b = blockIdx.y, i0 = blockIdx.x * 128, t = threadIdx.x;
    const int w = t >> 5, lane = t & 31;
    const size_t qkoff = (size_t)b * SYN * 64;

    // stage Q (cols 0..31) rows i0..+127 bf16 hi/lo at stride 80 (aliases P region)
#pragma unroll
    for (int u = 0; u < 4; u++) {
        int id = t + 256 * u;
        int half = id >> 9, idx = id & 511, row = idx >> 2, ch = idx & 3;
        const unsigned short* src = (half ? g_ql : g_qh) + qkoff + (size_t)(i0 + row) * 64 + ch * 8;
        cp_async16(smb + (unsigned)half * 10240 + (unsigned)row * 80 + ch * 16, src);
    }
    CP_COMMIT();

    auto issue_K = [&](int jt, int buf) {
#pragma unroll
        for (int u = 0; u < 2; u++) {
            int id = t + 256 * u;
            int half = id >> 8, idx = id & 255, row = idx >> 2, ch = idx & 3;
            const unsigned short* src = (half ? g_ql : g_qh) + qkoff +
                                        (size_t)(jt * 64 + row) * 64 + 32 + ch * 8;
            cp_async16(smb + 32768 + (unsigned)buf * 10240 + (unsigned)half * 5120 +
                       (unsigned)row * 80 + ch * 16, src);
        }
    };
    auto issue_V = [&](int jt) {
        const char* src = (const char*)g_vt + (size_t)(b * 32 + jt) * 16384;
        unsigned dst = smb + 53248 + (unsigned)(jt & 1) * 18432;
#pragma unroll
        for (int u = 0; u < 4; u++) {
            int ch = t + 256 * u;
            cp_async16(dst + (unsigned)(ch >> 3) * 144 + (unsigned)(ch & 7) * 16,
                       src + (size_t)ch * 16);
        }
    };
    issue_K(0, 0); issue_V(0); CP_COMMIT();
    CP_WAIT(0);
    __syncthreads();

    // Q fragments in registers (whole kernel)
    unsigned qh[2][4], ql[2][4];
#pragma unroll
    for (int kk = 0; kk < 2; kk++) {
        unsigned qa = smb + (unsigned)(w * 16 + (lane & 15)) * 80 + ((lane >> 4) << 4) + kk * 32;
        LDSM4(qh[kk], qa);
        LDSM4(ql[kk], qa + 10240);
    }
    __syncthreads();   // staging freed; P writes start below

    const int rlo = w * 16 + (lane >> 2), rhi = rlo + 8;
    const unsigned q4 = (lane & 3) * 4;
    const unsigned brow = (unsigned)(lane & 15) * 144 + (unsigned)(lane >> 4) * 16;
    float l0 = 0.f, l1 = 0.f;
    float acc[8][4];
#pragma unroll
    for (int n = 0; n < 8; n++)
#pragma unroll
        for (int e = 0; e < 4; e++) acc[n][e] = 0.f;

    for (int jt = 0; jt < 32; jt++) {
        const int cur = jt & 1;
        if (jt + 1 < 32) { issue_K(jt + 1, cur ^ 1); issue_V(jt + 1); CP_COMMIT(); }

        // ---- QK^T on HMMA (split bf16, 3 combos) ----
        float s[8][4];
#pragma unroll
        for (int n = 0; n < 8; n++)
#pragma unroll
            for (int e = 0; e < 4; e++) s[n][e] = 0.f;
        const unsigned kbase = smb + 32768 + (unsigned)cur * 10240;
#pragma unroll
        for (int nt = 0; nt < 8; nt++) {
            unsigned ka = kbase + (unsigned)(nt * 8 + (lane & 7)) * 80 + (lane >> 3) * 16;
            unsigned bh[4], bl[4];
            LDSM4(bh, ka);
            LDSM4(bl, ka + 5120);
            MMA16816(s[nt], qh[0], bh[0], bh[1]);
            MMA16816(s[nt], qh[1], bh[2], bh[3]);
            MMA16816(s[nt], qh[0], bl[0], bl[1]);
            MMA16816(s[nt], qh[1], bl[2], bl[3]);
            MMA16816(s[nt], ql[0], bh[0], bh[1]);
            MMA16816(s[nt], ql[1], bh[2], bh[3]);
        }
        // ---- exp (max-free) + row sums + P store (bf16 hi/lo, XOR swizzle) ----
        float slo = 0.f, shi = 0.f;
#pragma unroll
        for (int nt = 0; nt < 8; nt++) {
            s[nt][0] = __expf(s[nt][0]); s[nt][1] = __expf(s[nt][1]);
            s[nt][2] = __expf(s[nt][2]); s[nt][3] = __expf(s[nt][3]);
            slo += s[nt][0] + s[nt][1];
            shi += s[nt][2] + s[nt][3];
            unsigned hA, hB, lA, lB;
            CVTBF2(hA, s[nt][0], s[nt][1]);
            CVTBF2(hB, s[nt][2], s[nt][3]);
            CVTBF2(lA, s[nt][0] - __uint_as_float(hA << 16),
                       s[nt][1] - __uint_as_float(hA & 0xFFFF0000u));
            CVTBF2(lB, s[nt][2] - __uint_as_float(hB << 16),
                       s[nt][3] - __uint_as_float(hB & 0xFFFF0000u));
            unsigned oL = (unsigned)rlo * 128 + (((unsigned)(nt ^ (rlo & 7))) << 4) + q4;
            unsigned oH = (unsigned)rhi * 128 + (((unsigned)(nt ^ (rhi & 7))) << 4) + q4;
            *(unsigned*)(sm + oL) = hA;
            *(unsigned*)(sm + oH) = hB;
            *(unsigned*)(sm + 16384 + oL) = lA;
            *(unsigned*)(sm + 16384 + oH) = lB;
        }
        slo += __shfl_xor_sync(0xFFFFFFFFu, slo, 1);
        slo += __shfl_xor_sync(0xFFFFFFFFu, slo, 2);
        shi += __shfl_xor_sync(0xFFFFFFFFu, shi, 1);
        shi += __shfl_xor_sync(0xFFFFFFFFu, shi, 2);
        l0 += slo; l1 += shi;
        __syncwarp();

        // ---- PV on HMMA ----
        const unsigned vb = smb + 53248 + (unsigned)cur * 18432;
#pragma unroll
        for (int kk = 0; kk < 4; kk++) {
            int prow = w * 16 + (lane & 15);
            unsigned cj = (unsigned)(kk * 2 + (lane >> 4));
            unsigned pa = smb + (unsigned)prow * 128 + ((cj ^ (unsigned)(prow & 7)) << 4);
            unsigned ah[4], al[4];
            LDSM4(ah, pa);
            LDSM4(al, pa + 16384);
            unsigned bo = vb + brow + (unsigned)kk * 2304;
#pragma unroll
            for (int np = 0; np < 4; np++) {
                unsigned bb = bo + (unsigned)np * 32;
                unsigned bh[4], bl[4];
                LDSM4T(bh, bb);
                LDSM4T(bl, bb + 9216);
                MMA16816(acc[2*np],     ah, bh[0], bh[1]);
                MMA16816(acc[2*np],     ah, bl[0], bl[1]);
                MMA16816(acc[2*np],     al, bh[0], bh[1]);
                MMA16816(acc[2*np + 1], ah, bh[2], bh[3]);
                MMA16816(acc[2*np + 1], ah, bl[2], bl[3]);
                MMA16816(acc[2*np + 1], al, bh[2], bh[3]);
            }
        }
        if (jt + 1 < 32) CP_WAIT(0);
        __syncthreads();
    }

    // ---- epilogue ----
    if ((lane & 3) == 0) { slm[rlo] = l0; slm[rhi] = l1; }
    __syncthreads();
    const float il0 = 1.0f / slm[rlo], il1 = 1.0f / slm[rhi];
#pragma unroll
    for (int nt = 0; nt < 8; nt++) {
        int c = nt * 8 + (lane & 3) * 2;
        osm[rlo * 68 + c]     = acc[nt][0] * il0;
        osm[rlo * 68 + c + 1] = acc[nt][1] * il0;
        osm[rhi * 68 + c]     = acc[nt][2] * il1;
        osm[rhi * 68 + c + 1] = acc[nt][3] * il1;
    }
    __syncthreads();
    float* ob = g_o + (size_t)b * 64 * SYN;
#pragma unroll
    for (int u = 0; u < 32; u++) {
        int id = t + 256 * u, c = id >> 7, il = id & 127;
        ob[(size_t)c * SYN + i0 + il] = osm[il * 68 + c];
    }
}

// ---------------- K4 ----------------
__global__ void k4_stats(const float* __restrict__ gamma, const float* __restrict__ bn_w,
                         const float* __restrict__ bn_b) {
    __shared__ float rs[256], rq[256];
    const int c = blockIdx.x, t = threadIdx.x;
    float s = 0.f, s2 = 0.f;
    for (int b = 0; b < NB; b++) {
        const float* p = g_o + ((size_t)b * 64 + c) * SYN + t * 8;
#pragma unroll
        for (int u = 0; u < 2; u++) {
            float4 v = *(const float4*)(p + u * 4);
            s += (v.x + v.y) + (v.z + v.w);
            s2 += (v.x*v.x + v.y*v.y) + (v.z*v.z + v.w*v.w);
        }
    }
    rs[t] = s; rq[t] = s2;
    __syncthreads();
    for (int st = 128; st > 0; st >>= 1) {
        if (t < st) { rs[t] += rs[t + st]; rq[t] += rq[t + st]; }
        __syncthreads();
    }
    if (t == 0) {
        const float N = 16384.f;
        float mean = rs[0] / N, var = rq[0] / N - mean * mean;
        float g = gamma[0];
        float inv = rsqrtf(g * g * var + 1e-5f);
        float sc = g * inv * bn_w[c];
        g_scale[c] = sc;
        g_shift[c] = bn_b[c] - mean * sc;
    }
}

// ---------------- K5 ----------------
__global__ void k5_out(const float* __restrict__ x, float* __restrict__ out) {
    int idx = blockIdx.x * 256 + threadIdx.x;
    int c = (idx >> 11) & 63;
    float add = fmaf(g_scale[c], g_o[idx], g_shift[c]);
    float4 xv = ((const float4*)x)[idx];
    ((float4*)out)[idx] = make_float4(xv.x + add, xv.y + add, xv.z + add, xv.w + add);
}

// ---------------- launcher ----------------
extern "C" void kernel_launch(void* const* d_in, const int* in_sizes, int n_in,
                              void* d_out, int out_size) {
    const float* x     = (const float*)d_in[0];
    const float* y     = (const float*)d_in[1];
    const float* wq    = (const float*)d_in[2];
    const float* bq    = (const float*)d_in[3];
    const float* wk    = (const float*)d_in[4];
    const float* bk    = (const float*)d_in[5];
    const float* wv    = (const float*)d_in[6];
    const float* bv    = (const float*)d_in[7];
    const float* gamma = (const float*)d_in[8];
    const float* bn_w  = (const float*)d_in[9];
    const float* bn_b  = (const float*)d_in[10];
    float* out = (float*)d_out;

    cudaFuncSetAttribute(k3_attn, cudaFuncAttributeMaxDynamicSharedMemorySize, K3_SMEM);
    k0_transpose<<<80, 256>>>(wq, wk, wv);
    k1_proj_qk<<<dim3(16, NB), 256>>>(y, bq, bk);
    k2_proj_v<<<dim3(16, NB), 256>>>(x, bv);
    k3_attn<<<dim3(16, NB), 256, K3_SMEM>>>();
    k4_stats<<<64, 256>>>(gamma, bn_w, bn_b);
    k5_out<<<4096, 256>>>(x, out);
}

// round 9
// speedup vs baseline: 2.4525x; 1.0334x over previous
#include <cuda_runtime.h>
#include <cuda_bf16.h>

#define NB 8
#define SXN 8192
#define CYC 256
#define SYN 2048

__device__ __align__(16) float g_wt[CYC * 64];
__device__ __align__(16) float g_wvt[64 * 64];
__device__ __align__(16) unsigned short g_qh[(size_t)NB * SYN * 64]; // [s][0:32 q|32:64 k] hi
__device__ __align__(16) unsigned short g_ql[(size_t)NB * SYN * 64]; // lo
__device__ __align__(16) unsigned short g_vt[(size_t)NB * 32 * 8192]; // [b][jt][hi 64x64|lo 64x64]
__device__ __align__(16) float g_o[(size_t)NB * 64 * SYN];
__device__ float g_scale[64];
__device__ float g_shift[64];

__device__ __forceinline__ float2 ffma2(float2 a, float2 b, float2 c) {
    unsigned long long ra = *reinterpret_cast<unsigned long long*>(&a);
    unsigned long long rb = *reinterpret_cast<unsigned long long*>(&b);
    unsigned long long rc = *reinterpret_cast<unsigned long long*>(&c);
    unsigned long long rd;
    asm("fma.rn.f32x2 %0, %1, %2, %3;" : "=l"(rd) : "l"(ra), "l"(rb), "l"(rc));
    return *reinterpret_cast<float2*>(&rd);
}
__device__ __forceinline__ float2 fdup(float x) { return make_float2(x, x); }
__device__ __forceinline__ void cp_async16(unsigned s, const void* g) {
    asm volatile("cp.async.cg.shared.global [%0], [%1], 16;" :: "r"(s), "l"(g));
}
#define CP_COMMIT() asm volatile("cp.async.commit_group;")
#define CP_WAIT(n)  asm volatile("cp.async.wait_group %0;" :: "n"(n))
__device__ __forceinline__ unsigned smem_u32(const void* p) {
    unsigned a;
    asm("{ .reg .u64 t; cvta.to.shared.u64 t, %1; cvt.u32.u64 %0, t; }" : "=r"(a) : "l"(p));
    return a;
}
#define CVTBF2(r, a, b) asm("cvt.rn.satfinite.bf16x2.f32 %0, %1, %2;" : "=r"(r) : "f"(b), "f"(a))
#define LDSM4(r, addr) asm volatile( \
    "ldmatrix.sync.aligned.m8n8.x4.shared.b16 {%0,%1,%2,%3}, [%4];" \
    : "=r"((r)[0]), "=r"((r)[1]), "=r"((r)[2]), "=r"((r)[3]) : "r"(addr))
#define LDSM4T(r, addr) asm volatile( \
    "ldmatrix.sync.aligned.m8n8.x4.trans.shared.b16 {%0,%1,%2,%3}, [%4];" \
    : "=r"((r)[0]), "=r"((r)[1]), "=r"((r)[2]), "=r"((r)[3]) : "r"(addr))
#define MMA16816(d, a, b0, b1) asm volatile( \
    "mma.sync.aligned.m16n8k16.row.col.f32.bf16.bf16.f32 " \
    "{%0,%1,%2,%3}, {%4,%5,%6,%7}, {%8,%9}, {%0,%1,%2,%3};" \
    : "+f"((d)[0]), "+f"((d)[1]), "+f"((d)[2]), "+f"((d)[3]) \
    : "r"((a)[0]), "r"((a)[1]), "r"((a)[2]), "r"((a)[3]), "r"(b0), "r"(b1))

__device__ __forceinline__ unsigned short f2bf(float v) {
    __nv_bfloat16 h = __float2bfloat16(v);
    return *reinterpret_cast<unsigned short*>(&h);
}
__device__ __forceinline__ float bfhi(unsigned short h) {
    return __uint_as_float((unsigned)h << 16);
}

// ---------------- K0 ----------------
__global__ void k0_transpose(const float* __restrict__ wq, const float* __restrict__ wk,
                             const float* __restrict__ wv) {
    int id = blockIdx.x * 256 + threadIdx.x;
    if (id < 16384) {
        int c = id & 255, n = id >> 8;
        g_wt[c * 64 + n] = (n < 32) ? wq[n * 256 + c] : wk[(n - 32) * 256 + c];
    } else if (id < 20480) {
        int i2 = id - 16384, c = i2 & 63, n = i2 >> 6;
        g_wvt[c * 64 + n] = wv[n * 64 + c];
    }
}

// ---------------- K1: q/k projection -> bf16 hi/lo ----------------
__global__ __launch_bounds__(256) void k1_proj_qk(const float* __restrict__ y,
                                                  const float* __restrict__ bq,
                                                  const float* __restrict__ bk) {
    __shared__ __align__(16) float As[16][128];
    __shared__ __align__(16) float Bs[16][68];
    const int b = blockIdx.y, s0 = blockIdx.x * 128, t = threadIdx.x;
    const int tm = t & 15, tn = t >> 4;
    const int lk = t >> 4, lm = (t & 15) * 8;
    const int bn = t & 63, bk4 = t >> 6;
    float2 acc[8][2];
#pragma unroll
    for (int i = 0; i < 8; i++) { acc[i][0] = make_float2(0.f,0.f); acc[i][1] = make_float2(0.f,0.f); }
    const float* yb = y + (size_t)b * CYC * SYN + s0;
    for (int c0 = 0; c0 < CYC; c0 += 16) {
        float4 va = *(const float4*)(yb + (size_t)(c0 + lk) * SYN + lm);
        float4 vb = *(const float4*)(yb + (size_t)(c0 + lk) * SYN + lm + 4);
        float w4[4];
#pragma unroll
        for (int e = 0; e < 4; e++) w4[e] = g_wt[(size_t)(c0 + bk4 * 4 + e) * 64 + bn];
        __syncthreads();
        *(float4*)&As[lk][lm] = va; *(float4*)&As[lk][lm + 4] = vb;
#pragma unroll
        for (int e = 0; e < 4; e++) Bs[bk4 * 4 + e][bn] = w4[e];
        __syncthreads();
#pragma unroll
        for (int k = 0; k < 16; k++) {
            float4 a0 = *(const float4*)&As[k][tm * 4];
            float4 a1 = *(const float4*)&As[k][64 + tm * 4];
            float4 bb = *(const float4*)&Bs[k][tn * 4];
            float2 b01 = make_float2(bb.x, bb.y), b23 = make_float2(bb.z, bb.w);
            float am[8] = {a0.x, a0.y, a0.z, a0.w, a1.x, a1.y, a1.z, a1.w};
#pragma unroll
            for (int mi = 0; mi < 8; mi++) {
                float2 ad = fdup(am[mi]);
                acc[mi][0] = ffma2(ad, b01, acc[mi][0]);
                acc[mi][1] = ffma2(ad, b23, acc[mi][1]);
            }
        }
    }
    const int n0 = tn * 4;
    float bias[4];
#pragma unroll
    for (int e = 0; e < 4; e++) { int n = n0 + e; bias[e] = (n < 32) ? bq[n] : bk[n - 32]; }
#pragma unroll
    for (int mi = 0; mi < 8; mi++) {
        int m = (mi < 4) ? (tm * 4 + mi) : (64 + tm * 4 + (mi - 4));
        float v0 = acc[mi][0].x + bias[0], v1 = acc[mi][0].y + bias[1];
        float v2 = acc[mi][1].x + bias[2], v3 = acc[mi][1].y + bias[3];
        unsigned short h0 = f2bf(v0), h1 = f2bf(v1), h2 = f2bf(v2), h3 = f2bf(v3);
        size_t o = ((size_t)b * SYN + s0 + m) * 64 + n0;
        *(ushort4*)&g_qh[o] = make_ushort4(h0, h1, h2, h3);
        *(ushort4*)&g_ql[o] = make_ushort4(
            f2bf(v0 - bfhi(h0)), f2bf(v1 - bfhi(h1)),
            f2bf(v2 - bfhi(h2)), f2bf(v3 - bfhi(h3)));
    }
}

// ---------------- K2: pooled v proj -> bf16 hi/lo V tiles -------------------
__global__ __launch_bounds__(256) void k2_proj_v(const float* __restrict__ x,
                                                 const float* __restrict__ bv) {
    __shared__ __align__(16) float As[16][128];
    __shared__ __align__(16) float Bs[16][68];
    const int b = blockIdx.y, j0 = blockIdx.x * 128, t = threadIdx.x;
    const int tm = t & 15, tn = t >> 4;
    const int lr = t >> 4, f4 = t & 15;
    const int bn = t & 63, bk4 = t >> 6;
    float2 acc[8][2];
#pragma unroll
    for (int i = 0; i < 8; i++) { acc[i][0] = make_float2(0.f,0.f); acc[i][1] = make_float2(0.f,0.f); }
    for (int c0 = 0; c0 < 64; c0 += 16) {
        const float* xb = x + ((size_t)b * 64 + c0 + lr) * SXN + (size_t)j0 * 4;
        float av[8];
#pragma unroll
        for (int e = 0; e < 8; e++) {
            float4 v = *(const float4*)(xb + (size_t)(f4 + 16 * e) * 4);
            av[e] = (v.x + v.y) + (v.z + v.w);
        }
        float w4[4];
#pragma unroll
        for (int e = 0; e < 4; e++) w4[e] = g_wvt[(size_t)(c0 + bk4 * 4 + e) * 64 + bn];
        __syncthreads();
#pragma unroll
        for (int e = 0; e < 8; e++) As[lr][f4 + 16 * e] = av[e];
#pragma unroll
        for (int e = 0; e < 4; e++) Bs[bk4 * 4 + e][bn] = w4[e];
        __syncthreads();
#pragma unroll
        for (int k = 0; k < 16; k++) {
            float4 a0 = *(const float4*)&As[k][tm * 4];
            float4 a1 = *(const float4*)&As[k][64 + tm * 4];
            float4 bb = *(const float4*)&Bs[k][tn * 4];
            float2 b01 = make_float2(bb.x, bb.y), b23 = make_float2(bb.z, bb.w);
            float am[8] = {a0.x, a0.y, a0.z, a0.w, a1.x, a1.y, a1.z, a1.w};
#pragma unroll
            for (int mi = 0; mi < 8; mi++) {
                float2 ad = fdup(am[mi]);
                acc[mi][0] = ffma2(ad, b01, acc[mi][0]);
                acc[mi][1] = ffma2(ad, b23, acc[mi][1]);
            }
        }
    }
    const int n0 = tn * 4;
    float bias[4];
#pragma unroll
    for (int e = 0; e < 4; e++) bias[e] = 4.0f * bv[n0 + e];
#pragma unroll
    for (int mi = 0; mi < 8; mi++) {
        int m = (mi < 4) ? (tm * 4 + mi) : (64 + tm * 4 + (mi - 4));
        int jt = blockIdx.x * 2 + (m >> 6), jl = m & 63;
        size_t be = (size_t)(b * 32 + jt) * 8192;
        float v0 = acc[mi][0].x + bias[0], v1 = acc[mi][0].y + bias[1];
        float v2 = acc[mi][1].x + bias[2], v3 = acc[mi][1].y + bias[3];
        unsigned short h0 = f2bf(v0), h1 = f2bf(v1), h2 = f2bf(v2), h3 = f2bf(v3);
        *(ushort4*)&g_vt[be + jl * 64 + n0] = make_ushort4(h0, h1, h2, h3);
        *(ushort4*)&g_vt[be + 4096 + jl * 64 + n0] = make_ushort4(
            f2bf(v0 - bfhi(h0)), f2bf(v1 - bfhi(h1)),
            f2bf(v2 - bfhi(h2)), f2bf(v3 - bfhi(h3)));
    }
}

// ---------------- K3: full HMMA attention, 512 threads ----------------
// warp w: rows 16*(w&7), n/ch-half nh=w>>3
// smem: P[hi 0..16K|lo 16..32K] (128B rows, XOR16 swizzle), Q staged over P
//       K 32768 + buf*10240 (hi stride80, lo +5120)
//       V 53248 + buf*18432 (stride 144, lo +9216)
//       slm 90112 (2x128 f32)   total 91136
#define K3_SMEM 91136

__global__ __launch_bounds__(512, 1) void k3_attn() {
    extern __shared__ char sm[];
    const unsigned smb = smem_u32(sm);
    float* slm = (float*)(sm + 90112);
    float* osm = (float*)sm;
    const int b = blockIdx.y, i0 = blockIdx.x * 128, t = threadIdx.x;
    const int w = t >> 5, lane = t & 31;
    const int wq = w & 7, nh = w >> 3;
    const size_t qkoff = (size_t)b * SYN * 64;

    // stage Q (cols 0..31) rows i0..+127 bf16 hi/lo at stride 80 (aliases P region)
#pragma unroll
    for (int u = 0; u < 2; u++) {
        int id = t + 512 * u;
        int half = id >> 9, idx = id & 511, row = idx >> 2, ch = idx & 3;
        const unsigned short* src = (half ? g_ql : g_qh) + qkoff + (size_t)(i0 + row) * 64 + ch * 8;
        cp_async16(smb + (unsigned)half * 10240 + (unsigned)row * 80 + ch * 16, src);
    }
    CP_COMMIT();

    auto issue_K = [&](int jt, int buf) {
        int half = t >> 8, idx = t & 255, row = idx >> 2, ch = idx & 3;
        const unsigned short* src = (half ? g_ql : g_qh) + qkoff +
                                    (size_t)(jt * 64 + row) * 64 + 32 + ch * 8;
        cp_async16(smb + 32768 + (unsigned)buf * 10240 + (unsigned)half * 5120 +
                   (unsigned)row * 80 + ch * 16, src);
    };
    auto issue_V = [&](int jt) {
        const char* src = (const char*)g_vt + (size_t)(b * 32 + jt) * 16384;
        unsigned dst = smb + 53248 + (unsigned)(jt & 1) * 18432;
#pragma unroll
        for (int u = 0; u < 2; u++) {
            int ch = t + 512 * u;
            cp_async16(dst + (unsigned)(ch >> 3) * 144 + (unsigned)(ch & 7) * 16,
                       src + (size_t)ch * 16);
        }
    };
    issue_K(0, 0); issue_V(0); CP_COMMIT();
    CP_WAIT(0);
    __syncthreads();

    // Q fragments in registers (whole kernel)
    unsigned qh[2][4], ql[2][4];
#pragma unroll
    for (int kk = 0; kk < 2; kk++) {
        unsigned qa = smb + (unsigned)(wq * 16 + (lane & 15)) * 80 + ((lane >> 4) << 4) + kk * 32;
        LDSM4(qh[kk], qa);
        LDSM4(ql[kk], qa + 10240);
    }
    __syncthreads();   // staging freed; P writes start below

    const int rlo = wq * 16 + (lane >> 2), rhi = rlo + 8;
    const unsigned q4 = (lane & 3) * 4;
    const unsigned brow = (unsigned)(lane & 15) * 144 + (unsigned)(lane >> 4) * 16;
    float l0 = 0.f, l1 = 0.f;
    float acc[4][4];
#pragma unroll
    for (int n = 0; n < 4; n++)
#pragma unroll
        for (int e = 0; e < 4; e++) acc[n][e] = 0.f;

    for (int jt = 0; jt < 32; jt++) {
        const int cur = jt & 1;
        if (jt + 1 < 32) { issue_K(jt + 1, cur ^ 1); issue_V(jt + 1); CP_COMMIT(); }

        // ---- QK^T on HMMA (split bf16, 3 combos), 4 n-tiles of this half ----
        float s[4][4];
#pragma unroll
        for (int n = 0; n < 4; n++)
#pragma unroll
            for (int e = 0; e < 4; e++) s[n][e] = 0.f;
        const unsigned kbase = smb + 32768 + (unsigned)cur * 10240;
#pragma unroll
        for (int nt = 0; nt < 4; nt++) {
            int ntg = nh * 4 + nt;
            unsigned ka = kbase + (unsigned)(ntg * 8 + (lane & 7)) * 80 + (lane >> 3) * 16;
            unsigned bh[4], bl[4];
            LDSM4(bh, ka);
            LDSM4(bl, ka + 5120);
            MMA16816(s[nt], qh[0], bh[0], bh[1]);
            MMA16816(s[nt], qh[1], bh[2], bh[3]);
            MMA16816(s[nt], qh[0], bl[0], bl[1]);
            MMA16816(s[nt], qh[1], bl[2], bl[3]);
            MMA16816(s[nt], ql[0], bh[0], bh[1]);
            MMA16816(s[nt], ql[1], bh[2], bh[3]);
        }
        // ---- exp (max-free) + partial row sums + P store ----
        float slo = 0.f, shi = 0.f;
#pragma unroll
        for (int nt = 0; nt < 4; nt++) {
            int ntg = nh * 4 + nt;
            s[nt][0] = __expf(s[nt][0]); s[nt][1] = __expf(s[nt][1]);
            s[nt][2] = __expf(s[nt][2]); s[nt][3] = __expf(s[nt][3]);
            slo += s[nt][0] + s[nt][1];
            shi += s[nt][2] + s[nt][3];
            unsigned hA, hB, lA, lB;
            CVTBF2(hA, s[nt][0], s[nt][1]);
            CVTBF2(hB, s[nt][2], s[nt][3]);
            CVTBF2(lA, s[nt][0] - __uint_as_float(hA << 16),
                       s[nt][1] - __uint_as_float(hA & 0xFFFF0000u));
            CVTBF2(lB, s[nt][2] - __uint_as_float(hB << 16),
                       s[nt][3] - __uint_as_float(hB & 0xFFFF0000u));
            unsigned oL = (unsigned)rlo * 128 + (((unsigned)(ntg ^ (rlo & 7))) << 4) + q4;
            unsigned oH = (unsigned)rhi * 128 + (((unsigned)(ntg ^ (rhi & 7))) << 4) + q4;
            *(unsigned*)(sm + oL) = hA;
            *(unsigned*)(sm + oH) = hB;
            *(unsigned*)(sm + 16384 + oL) = lA;
            *(unsigned*)(sm + 16384 + oH) = lB;
        }
        slo += __shfl_xor_sync(0xFFFFFFFFu, slo, 1);
        slo += __shfl_xor_sync(0xFFFFFFFFu, slo, 2);
        shi += __shfl_xor_sync(0xFFFFFFFFu, shi, 1);
        shi += __shfl_xor_sync(0xFFFFFFFFu, shi, 2);
        l0 += slo; l1 += shi;
        __syncthreads();   // P complete (both halves) before PV reads

        // ---- PV on HMMA: rows 16wq..+15, channels nh*32..+31 ----
        const unsigned vb = smb + 53248 + (unsigned)cur * 18432;
#pragma unroll
        for (int kk = 0; kk < 4; kk++) {
            int prow = wq * 16 + (lane & 15);
            unsigned cj = (unsigned)(kk * 2 + (lane >> 4));
            unsigned pa = smb + (unsigned)prow * 128 + ((cj ^ (unsigned)(prow & 7)) << 4);
            unsigned ah[4], al[4];
            LDSM4(ah, pa);
            LDSM4(al, pa + 16384);
            unsigned bo = vb + brow + (unsigned)kk * 2304;
#pragma unroll
            for (int np = 0; np < 2; np++) {
                unsigned bb = bo + (unsigned)(nh * 2 + np) * 32;
                unsigned bh[4], bl[4];
                LDSM4T(bh, bb);
                LDSM4T(bl, bb + 9216);
                MMA16816(acc[2*np],     ah, bh[0], bh[1]);
                MMA16816(acc[2*np],     ah, bl[0], bl[1]);
                MMA16816(acc[2*np],     al, bh[0], bh[1]);
                MMA16816(acc[2*np + 1], ah, bh[2], bh[3]);
                MMA16816(acc[2*np + 1], ah, bl[2], bl[3]);
                MMA16816(acc[2*np + 1], al, bh[2], bh[3]);
            }
        }
        if (jt + 1 < 32) CP_WAIT(0);
        __syncthreads();   // all PV reads done; next tile may overwrite P/buffers
    }

    // ---- epilogue: combine half l-sums, normalize, transpose store ----
    if ((lane & 3) == 0) { slm[nh * 128 + rlo] = l0; slm[nh * 128 + rhi] = l1; }
    __syncthreads();
    const float il0 = 1.0f / (slm[rlo] + slm[128 + rlo]);
    const float il1 = 1.0f / (slm[rhi] + slm[128 + rhi]);
#pragma unroll
    for (int nt = 0; nt < 4; nt++) {
        int c = nh * 32 + nt * 8 + (lane & 3) * 2;
        osm[rlo * 68 + c]     = acc[nt][0] * il0;
        osm[rlo * 68 + c + 1] = acc[nt][1] * il0;
        osm[rhi * 68 + c]     = acc[nt][2] * il1;
        osm[rhi * 68 + c + 1] = acc[nt][3] * il1;
    }
    __syncthreads();
    float* ob = g_o + (size_t)b * 64 * SYN;
#pragma unroll
    for (int u = 0; u < 16; u++) {
        int id = t + 512 * u, c = id >> 7, il = id & 127;
        ob[(size_t)c * SYN + i0 + il] = osm[il * 68 + c];
    }
}

// ---------------- K4 ----------------
__global__ void k4_stats(const float* __restrict__ gamma, const float* __restrict__ bn_w,
                         const float* __restrict__ bn_b) {
    __shared__ float rs[256], rq[256];
    const int c = blockIdx.x, t = threadIdx.x;
    float s = 0.f, s2 = 0.f;
    for (int b = 0; b < NB; b++) {
        const float* p = g_o + ((size_t)b * 64 + c) * SYN + t * 8;
#pragma unroll
        for (int u = 0; u < 2; u++) {
            float4 v = *(const float4*)(p + u * 4);
            s += (v.x + v.y) + (v.z + v.w);
            s2 += (v.x*v.x + v.y*v.y) + (v.z*v.z + v.w*v.w);
        }
    }
    rs[t] = s; rq[t] = s2;
    __syncthreads();
    for (int st = 128; st > 0; st >>= 1) {
        if (t < st) { rs[t] += rs[t + st]; rq[t] += rq[t + st]; }
        __syncthreads();
    }
    if (t == 0) {
        const float N = 16384.f;
        float mean = rs[0] / N, var = rq[0] / N - mean * mean;
        float g = gamma[0];
        float inv = rsqrtf(g * g * var + 1e-5f);
        float sc = g * inv * bn_w[c];
        g_scale[c] = sc;
        g_shift[c] = bn_b[c] - mean * sc;
    }
}

// ---------------- K5 ----------------
__global__ void k5_out(const float* __restrict__ x, float* __restrict__ out) {
    int idx = blockIdx.x * 256 + threadIdx.x;
    int c = (idx >> 11) & 63;
    float add = fmaf(g_scale[c], g_o[idx], g_shift[c]);
    float4 xv = ((const float4*)x)[idx];
    ((float4*)out)[idx] = make_float4(xv.x + add, xv.y + add, xv.z + add, xv.w + add);
}

// ---------------- launcher ----------------
extern "C" void kernel_launch(void* const* d_in, const int* in_sizes, int n_in,
                              void* d_out, int out_size) {
    const float* x     = (const float*)d_in[0];
    const float* y     = (const float*)d_in[1];
    const float* wq    = (const float*)d_in[2];
    const float* bq    = (const float*)d_in[3];
    const float* wk    = (const float*)d_in[4];
    const float* bk    = (const float*)d_in[5];
    const float* wv    = (const float*)d_in[6];
    const float* bv    = (const float*)d_in[7];
    const float* gamma = (const float*)d_in[8];
    const float* bn_w  = (const float*)d_in[9];
    const float* bn_b  = (const float*)d_in[10];
    float* out = (float*)d_out;

    cudaFuncSetAttribute(k3_attn, cudaFuncAttributeMaxDynamicSharedMemorySize, K3_SMEM);
    k0_transpose<<<80, 256>>>(wq, wk, wv);
    k1_proj_qk<<<dim3(16, NB), 256>>>(y, bq, bk);
    k2_proj_v<<<dim3(16, NB), 256>>>(x, bv);
    k3_attn<<<dim3(16, NB), 512, K3_SMEM>>>();
    k4_stats<<<64, 256>>>(gamma, bn_w, bn_b);
    k5_out<<<4096, 256>>>(x, out);
}